// round 6
// baseline (speedup 1.0000x reference)
#include <cuda_runtime.h>
#include <cuda_bf16.h>
#include <math.h>

#define BB 2
#define NRES 384
#define CS 256
#define CZ 128
#define NODE_IN 145
#define HP 132           // Hs pitch (floats)
#define NROWS 8          // rows per CTA in node_mlp
#define PI_F 3.14159265358979323846f

typedef unsigned long long u64;

// ---------------- packed f32x2 helpers (Blackwell FFMA2) ----------------
__device__ __forceinline__ void ffma2(u64 &d, u64 a, u64 b) {
    asm("fma.rn.f32x2 %0, %1, %2, %0;" : "+l"(d) : "l"(a), "l"(b));
}
__device__ __forceinline__ u64 pack2(float x) {
    u64 r; asm("mov.b64 %0, {%1, %1};" : "=l"(r) : "f"(x)); return r;
}
__device__ __forceinline__ float2 unpack2(u64 v) {
    float2 f; asm("mov.b64 {%0, %1}, %2;" : "=f"(f.x), "=f"(f.y) : "l"(v)); return f;
}

// ---------------- scratch (no allocation allowed) ----------------
__device__ float g_NIN[BB * NRES * NODE_IN];   // node_in
__device__ float g_NA [BB * NRES * CZ];        // prot_i @ ew1[0:73]
__device__ float g_NB [BB * NRES * CZ];        // prot_j @ ew1[73:146]
__device__ float g_REL[767 * CZ];              // idx_emb(rel) @ ew1[146:178]

// ---------------- kernel 1: per-node features + A/B projections ----------------
__global__ __launch_bounds__(128) void prep_node_kernel(
    const float* __restrict__ atom10, const int* __restrict__ seq_idx,
    const float* __restrict__ t, const float* __restrict__ fixed_mask,
    const float* __restrict__ sc_trans, const float* __restrict__ sc_rots,
    const float* __restrict__ sc_atom14, const float* __restrict__ ew1)
{
    __shared__ float pt[73];
    __shared__ float nin[NODE_IN];
    const int row = blockIdx.x;           // b*NRES + i
    const int b = row / NRES;
    const int tid = threadIdx.x;

    if (tid < 16) {
        float fr = expf((float)tid * (-logf(10000.0f) / 15.0f));
        float ang = t[b] * 10000.0f * fr;
        pt[tid]      = sinf(ang);
        pt[16 + tid] = cosf(ang);
        float den = powf(2056.0f, (float)tid / 16.0f);
        float ang2 = (float)seq_idx[row] * PI_F / den;
        nin[73 + tid]      = sinf(ang2);
        nin[73 + 16 + tid] = cosf(ang2);
    }
    if (tid == 0) pt[32] = fixed_mask[row];
    if (tid < 30) pt[33 + tid] = atom10[row * 30 + tid];
    if (tid < 10) {
        const float* ap = atom10 + row * 30 + tid * 3;
        float x = ap[0], y = ap[1], z = ap[2];
        float d = sqrtf(x * x + y * y + z * z);
        pt[63 + tid] = 1.0f / (1.0f + d * d);
        const float* tr = sc_trans + row * 3;
        const float* R  = sc_rots  + row * 9;
        const float* at = sc_atom14 + row * 42 + (4 + tid) * 3;
        float d0 = at[0] - tr[0], d1 = at[1] - tr[1], d2 = at[2] - tr[2];
        float l0 = d0 * R[0] + d1 * R[3] + d2 * R[6];
        float l1 = d0 * R[1] + d1 * R[4] + d2 * R[7];
        float l2 = d0 * R[2] + d1 * R[5] + d2 * R[8];
        nin[105 + tid * 3 + 0] = l0;
        nin[105 + tid * 3 + 1] = l1;
        nin[105 + tid * 3 + 2] = l2;
        float ld = sqrtf(l0 * l0 + l1 * l1 + l2 * l2);
        nin[135 + tid] = 1.0f / (1.0f + ld);
    }
    __syncthreads();
    if (tid < 73) nin[tid] = pt[tid];
    __syncthreads();

    for (int x = tid; x < NODE_IN; x += 128)
        g_NIN[row * NODE_IN + x] = nin[x];

    if (tid < CZ) {
        float accA = 0.f, accB = 0.f;
        #pragma unroll 4
        for (int f = 0; f < 73; f++) {
            float p = pt[f];
            accA = fmaf(p, ew1[f * CZ + tid], accA);
            accB = fmaf(p, ew1[(73 + f) * CZ + tid], accB);
        }
        g_NA[row * CZ + tid] = accA;
        g_NB[row * CZ + tid] = accB;
    }
}

// ---------------- kernel 2: relative-position table ----------------
__global__ __launch_bounds__(128) void prep_rel_kernel(const float* __restrict__ ew1)
{
    __shared__ float emb[32];
    const int r = blockIdx.x;             // rel = r - 383
    const int tid = threadIdx.x;
    if (tid < 16) {
        float v = (float)(r - 383);
        float den = powf(2056.0f, (float)tid / 16.0f);
        float ang = v * PI_F / den;
        emb[tid]      = sinf(ang);
        emb[16 + tid] = cosf(ang);
    }
    __syncthreads();
    float acc = 0.f;
    #pragma unroll
    for (int k = 0; k < 32; k++)
        acc = fmaf(emb[k], ew1[(146 + k) * CZ + tid], acc);
    g_REL[r * CZ + tid] = acc;
}

// ---------------- kernel 3: node MLP + LN (8 rows/CTA) ----------------
__global__ __launch_bounds__(256) void node_mlp_kernel(
    const float* __restrict__ nw1, const float* __restrict__ nb1,
    const float* __restrict__ nw2, const float* __restrict__ nb2,
    const float* __restrict__ nw3, const float* __restrict__ nb3,
    const float* __restrict__ ng,  const float* __restrict__ nbt,
    float* __restrict__ outN)
{
    __shared__ float nin[NROWS][NODE_IN];
    __shared__ float h[NROWS][CS];
    __shared__ float sred[NROWS][8], s2red[NROWS][8];
    const int r0 = blockIdx.x * NROWS;
    const int tid = threadIdx.x;

    for (int x = tid; x < NROWS * NODE_IN; x += 256)
        nin[x / NODE_IN][x % NODE_IN] = g_NIN[r0 * NODE_IN + x];
    __syncthreads();

    float a[NROWS];
    #pragma unroll
    for (int r = 0; r < NROWS; r++) a[r] = nb1[tid];
    #pragma unroll 4
    for (int k = 0; k < NODE_IN; k++) {
        float w = nw1[k * CS + tid];
        #pragma unroll
        for (int r = 0; r < NROWS; r++) a[r] = fmaf(nin[r][k], w, a[r]);
    }
    #pragma unroll
    for (int r = 0; r < NROWS; r++) h[r][tid] = fmaxf(a[r], 0.f);
    __syncthreads();

    #pragma unroll
    for (int r = 0; r < NROWS; r++) a[r] = nb2[tid];
    #pragma unroll 4
    for (int k = 0; k < CS; k++) {
        float w = nw2[k * CS + tid];
        #pragma unroll
        for (int r = 0; r < NROWS; r++) a[r] = fmaf(h[r][k], w, a[r]);
    }
    __syncthreads();
    #pragma unroll
    for (int r = 0; r < NROWS; r++) h[r][tid] = fmaxf(a[r], 0.f);
    __syncthreads();

    #pragma unroll
    for (int r = 0; r < NROWS; r++) a[r] = nb3[tid];
    #pragma unroll 4
    for (int k = 0; k < CS; k++) {
        float w = nw3[k * CS + tid];
        #pragma unroll
        for (int r = 0; r < NROWS; r++) a[r] = fmaf(h[r][k], w, a[r]);
    }

    #pragma unroll
    for (int r = 0; r < NROWS; r++) {
        float s = a[r], s2 = a[r] * a[r];
        #pragma unroll
        for (int o = 16; o > 0; o >>= 1) {
            s  += __shfl_xor_sync(0xffffffffu, s,  o);
            s2 += __shfl_xor_sync(0xffffffffu, s2, o);
        }
        if ((tid & 31) == 0) { sred[r][tid >> 5] = s; s2red[r][tid >> 5] = s2; }
    }
    __syncthreads();
    float gv = ng[tid], bv = nbt[tid];
    #pragma unroll
    for (int r = 0; r < NROWS; r++) {
        float S = 0.f, S2 = 0.f;
        #pragma unroll
        for (int w = 0; w < 8; w++) { S += sred[r][w]; S2 += s2red[r][w]; }
        float mu = S * (1.0f / CS);
        float var = S2 * (1.0f / CS) - mu * mu;
        float rs = rsqrtf(var + 1e-5f);
        outN[(r0 + r) * CS + tid] = (a[r] - mu) * rs * gv + bv;
    }
}

// ---------------- kernel 4: edge MLP (dominant) ----------------
// 256 threads, each owns 8(m) x 8(n): n in two contiguous groups
// [tx*4, tx*4+4) and [64+tx*4, 64+tx*4+4). FFMA2 pairs along m.
// Per k: 4 LDS.128 vs 32 FFMA2 -> fma-pipe bound.
__global__ __launch_bounds__(256, 1) void edge_kernel(
    const int* __restrict__ seq_idx, const float* __restrict__ sc_trans,
    const float* __restrict__ ew1, const float* __restrict__ eb1,
    const float* __restrict__ ew2, const float* __restrict__ eb2,
    const float* __restrict__ ew3, const float* __restrict__ eb3,
    const float* __restrict__ eg,  const float* __restrict__ ebt,
    float* __restrict__ outE)
{
    extern __shared__ float sm[];
    float* W2s  = sm;                       // 128*128
    float* W3s  = W2s + CZ * CZ;            // 128*128
    float* Hs   = W3s + CZ * CZ;            // 128*HP  (k-major: Hs[k][m])
    float* base = Hs + CZ * HP;             // 128
    int*  relS  = (int*)(base + CZ);        // 128
    int*  binS  = relS + CZ;                // 128

    const int jt = blockIdx.x, i = blockIdx.y, b = blockIdx.z;
    const int j0 = jt * 128;
    const int tid = threadIdx.x;
    const int row_i = b * NRES + i;

    // weights -> smem
    {
        const float4* w2v = (const float4*)ew2;
        const float4* w3v = (const float4*)ew3;
        float4* W2v = (float4*)W2s;
        float4* W3v = (float4*)W3s;
        for (int x = tid; x < (CZ * CZ) / 4; x += 256) { W2v[x] = w2v[x]; W3v[x] = w3v[x]; }
    }
    if (tid < CZ) base[tid] = g_NA[row_i * CZ + tid] + eb1[tid];
    if (tid >= 128) {
        const int m = tid - 128;
        const int j = j0 + m;
        const int row_j = b * NRES + j;
        int r = seq_idx[row_i] - seq_idx[row_j] + 383;
        relS[m] = min(max(r, 0), 766);
        float dx = sc_trans[row_i * 3 + 0] - sc_trans[row_j * 3 + 0];
        float dy = sc_trans[row_i * 3 + 1] - sc_trans[row_j * 3 + 1];
        float dz = sc_trans[row_i * 3 + 2] - sc_trans[row_j * 3 + 2];
        float d = sqrtf(dx * dx + dy * dy + dz * dz);
        int bin = -1;
        const double step = (20.0 - 1e-05) / 21.0;
        #pragma unroll
        for (int k = 0; k < 22; k++) {
            float lo = (float)(1e-05 + k * step);
            float hi = (k < 21) ? (float)(1e-05 + (k + 1) * step) : 1e8f;
            if (d > lo && d < hi) bin = k;
        }
        binS[m] = bin;
    }
    __syncthreads();

    // layer 1: h1[m][k] = relu(base[k] + B[j][k] + REL[rel][k] + dgram_row[k])
    {
        const int k = tid & 127;
        const int mb = (tid >> 7) * 64;
        const float bk = base[k];
        const float* nbp = g_NB + ((size_t)b * NRES + j0) * CZ + k;
        #pragma unroll 4
        for (int mm = 0; mm < 64; mm++) {
            const int m = mb + mm;
            float v = bk + nbp[(size_t)m * CZ] + g_REL[relS[m] * CZ + k];
            int bi = binS[m];
            if (bi >= 0) v += ew1[(178 + bi) * CZ + k];
            Hs[k * HP + m] = fmaxf(v, 0.f);
        }
    }
    __syncthreads();

    const int tx = tid & 15, ty = tid >> 4;
    const int n0a = tx * 4, n0b = 64 + tx * 4, m0 = ty * 8;

    // biases hoisted out of epilogues
    float bias2[8], bias3[8];
    #pragma unroll
    for (int c = 0; c < 4; c++) {
        bias2[c] = eb2[n0a + c]; bias2[4 + c] = eb2[n0b + c];
        bias3[c] = eb3[n0a + c]; bias3[4 + c] = eb3[n0b + c];
    }

    u64 acc[4][8];   // [m-pair][col: 0-3 -> n0a+c, 4-7 -> n0b+c-4]

    // ---- GEMM 1: h2 = relu(h1 @ W2 + b2) ----
    #pragma unroll
    for (int rp = 0; rp < 4; rp++)
        #pragma unroll
        for (int c = 0; c < 8; c++) acc[rp][c] = 0ULL;

    #pragma unroll 2
    for (int k = 0; k < CZ; k++) {
        ulonglong2 aA = *(const ulonglong2*)&Hs[k * HP + m0];
        ulonglong2 aB = *(const ulonglong2*)&Hs[k * HP + m0 + 4];
        float4 bva = *(const float4*)&W2s[k * CZ + n0a];
        float4 bvb = *(const float4*)&W2s[k * CZ + n0b];
        u64 bp[8];
        bp[0] = pack2(bva.x); bp[1] = pack2(bva.y); bp[2] = pack2(bva.z); bp[3] = pack2(bva.w);
        bp[4] = pack2(bvb.x); bp[5] = pack2(bvb.y); bp[6] = pack2(bvb.z); bp[7] = pack2(bvb.w);
        u64 av[4] = {aA.x, aA.y, aB.x, aB.y};
        #pragma unroll
        for (int rp = 0; rp < 4; rp++)
            #pragma unroll
            for (int c = 0; c < 8; c++)
                ffma2(acc[rp][c], av[rp], bp[c]);
    }

    float h2v[8][8];
    #pragma unroll
    for (int c = 0; c < 8; c++) {
        float bc = bias2[c];
        #pragma unroll
        for (int rp = 0; rp < 4; rp++) {
            float2 v = unpack2(acc[rp][c]);
            h2v[2 * rp][c]     = fmaxf(v.x + bc, 0.f);
            h2v[2 * rp + 1][c] = fmaxf(v.y + bc, 0.f);
        }
    }
    __syncthreads();
    // store h2 transposed back into Hs (k-major for GEMM2)
    #pragma unroll
    for (int c = 0; c < 8; c++) {
        const int ncol = (c < 4) ? (n0a + c) : (n0b + c - 4);
        *(float4*)&Hs[ncol * HP + m0] =
            make_float4(h2v[0][c], h2v[1][c], h2v[2][c], h2v[3][c]);
        *(float4*)&Hs[ncol * HP + m0 + 4] =
            make_float4(h2v[4][c], h2v[5][c], h2v[6][c], h2v[7][c]);
    }
    __syncthreads();

    // ---- GEMM 2: h3 = h2 @ W3 + b3 ----
    #pragma unroll
    for (int rp = 0; rp < 4; rp++)
        #pragma unroll
        for (int c = 0; c < 8; c++) acc[rp][c] = 0ULL;

    #pragma unroll 2
    for (int k = 0; k < CZ; k++) {
        ulonglong2 aA = *(const ulonglong2*)&Hs[k * HP + m0];
        ulonglong2 aB = *(const ulonglong2*)&Hs[k * HP + m0 + 4];
        float4 bva = *(const float4*)&W3s[k * CZ + n0a];
        float4 bvb = *(const float4*)&W3s[k * CZ + n0b];
        u64 bp[8];
        bp[0] = pack2(bva.x); bp[1] = pack2(bva.y); bp[2] = pack2(bva.z); bp[3] = pack2(bva.w);
        bp[4] = pack2(bvb.x); bp[5] = pack2(bvb.y); bp[6] = pack2(bvb.z); bp[7] = pack2(bvb.w);
        u64 av[4] = {aA.x, aA.y, aB.x, aB.y};
        #pragma unroll
        for (int rp = 0; rp < 4; rp++)
            #pragma unroll
            for (int c = 0; c < 8; c++)
                ffma2(acc[rp][c], av[rp], bp[c]);
    }

    float h3v[8][8];
    #pragma unroll
    for (int c = 0; c < 8; c++) {
        float bc = bias3[c];
        #pragma unroll
        for (int rp = 0; rp < 4; rp++) {
            float2 v = unpack2(acc[rp][c]);
            h3v[2 * rp][c]     = v.x + bc;
            h3v[2 * rp + 1][c] = v.y + bc;
        }
    }

    // ---- LayerNorm over n (128) per row m; reduce across 16 tx lanes ----
    float egv[8], ebv[8];
    #pragma unroll
    for (int c = 0; c < 4; c++) {
        egv[c] = eg[n0a + c];  ebv[c] = ebt[n0a + c];
        egv[4 + c] = eg[n0b + c]; ebv[4 + c] = ebt[n0b + c];
    }

    #pragma unroll
    for (int r = 0; r < 8; r++) {
        float s = 0.f, s2 = 0.f;
        #pragma unroll
        for (int c = 0; c < 8; c++) { float v = h3v[r][c]; s += v; s2 += v * v; }
        #pragma unroll
        for (int o = 8; o > 0; o >>= 1) {
            s  += __shfl_xor_sync(0xffffffffu, s,  o);
            s2 += __shfl_xor_sync(0xffffffffu, s2, o);
        }
        float mu = s * (1.0f / CZ);
        float var = s2 * (1.0f / CZ) - mu * mu;
        float rs = rsqrtf(var + 1e-5f);
        const int m = j0 + m0 + r;
        float* op = outE + ((((size_t)b * NRES + i) * NRES) + m) * CZ;
        *(float4*)(op + n0a) = make_float4(
            (h3v[r][0] - mu) * rs * egv[0] + ebv[0],
            (h3v[r][1] - mu) * rs * egv[1] + ebv[1],
            (h3v[r][2] - mu) * rs * egv[2] + ebv[2],
            (h3v[r][3] - mu) * rs * egv[3] + ebv[3]);
        *(float4*)(op + n0b) = make_float4(
            (h3v[r][4] - mu) * rs * egv[4] + ebv[4],
            (h3v[r][5] - mu) * rs * egv[5] + ebv[5],
            (h3v[r][6] - mu) * rs * egv[6] + ebv[6],
            (h3v[r][7] - mu) * rs * egv[7] + ebv[7]);
    }
}

// ---------------- launch ----------------
extern "C" void kernel_launch(void* const* d_in, const int* in_sizes, int n_in,
                              void* d_out, int out_size)
{
    const float* atom10     = (const float*)d_in[0];
    const int*   seq_idx    = (const int*)  d_in[1];
    const float* t          = (const float*)d_in[2];
    const float* fixed_mask = (const float*)d_in[3];
    /* d_in[4] node_mask unused */
    const float* sc_trans   = (const float*)d_in[5];
    const float* sc_rots    = (const float*)d_in[6];
    const float* sc_atom14  = (const float*)d_in[7];
    const float* nw1 = (const float*)d_in[8];
    const float* nb1 = (const float*)d_in[9];
    const float* nw2 = (const float*)d_in[10];
    const float* nb2 = (const float*)d_in[11];
    const float* nw3 = (const float*)d_in[12];
    const float* nb3 = (const float*)d_in[13];
    const float* ng  = (const float*)d_in[14];
    const float* nbt = (const float*)d_in[15];
    const float* ew1 = (const float*)d_in[16];
    const float* eb1 = (const float*)d_in[17];
    const float* ew2 = (const float*)d_in[18];
    const float* eb2 = (const float*)d_in[19];
    const float* ew3 = (const float*)d_in[20];
    const float* eb3 = (const float*)d_in[21];
    const float* eg  = (const float*)d_in[22];
    const float* ebt = (const float*)d_in[23];

    float* outN = (float*)d_out;
    float* outE = outN + (size_t)BB * NRES * CS;   // node first, then edge

    const int smem_edge = (CZ * CZ * 2 + CZ * HP + CZ) * 4 + 2 * CZ * 4;
    cudaFuncSetAttribute(edge_kernel, cudaFuncAttributeMaxDynamicSharedMemorySize, smem_edge);

    prep_node_kernel<<<BB * NRES, 128>>>(atom10, seq_idx, t, fixed_mask,
                                         sc_trans, sc_rots, sc_atom14, ew1);
    prep_rel_kernel<<<767, 128>>>(ew1);
    node_mlp_kernel<<<BB * NRES / NROWS, 256>>>(nw1, nb1, nw2, nb2, nw3, nb3, ng, nbt, outN);
    edge_kernel<<<dim3(NRES / 128, NRES, BB), 256, smem_edge>>>(
        seq_idx, sc_trans, ew1, eb1, ew2, eb2, ew3, eb3, eg, ebt, outE);
}

// round 9
// speedup vs baseline: 1.3818x; 1.3818x over previous
#include <cuda_runtime.h>
#include <cuda_bf16.h>
#include <math.h>
#include <stdint.h>

#define BB 2
#define NRES 384
#define CS 256
#define CZ 128
#define NODE_IN 145
#define NROWS 8
#define PI_F 3.14159265358979323846f

#define WPITCH 136                 // bf16 elems per weight row (272 B, conflict-free frag reads)
#define WTILE_B (128 * WPITCH * 2) // 34816 bytes per tile
#define H1PITCH 132                // floats

// smem byte offsets (edge kernel)
#define SM_W2H 0
#define SM_W2L 34816
#define SM_W3H 69632
#define SM_W3L 104448
#define SM_H1  139264
#define SM_AUX 206848
#define SMEM_TOTAL (SM_AUX + 3584)

// ---------------- scratch (no allocation allowed) ----------------
__device__ float g_NIN[BB * NRES * NODE_IN];
__device__ float g_NA [BB * NRES * CZ];            // prot_i @ ew1[0:73]
__device__ float g_NB [BB * NRES * CZ];            // prot_j @ ew1[73:146]
__device__ float g_REL[767 * CZ];                  // idx_emb(rel) @ ew1[146:178]
__device__ __nv_bfloat16 g_WT[4 * 128 * WPITCH];   // W2h, W2l, W3h, W3l  transposed [n][k]

// ---------------- helpers ----------------
// pack two f32 -> bf16x2, elem0(low 16 bits) = first arg
__device__ __forceinline__ uint32_t packbf(float lo, float hi) {
    uint32_t r;
    asm("cvt.rn.bf16x2.f32 %0, %1, %2;" : "=r"(r) : "f"(hi), "f"(lo));
    return r;
}
__device__ __forceinline__ void mma16816(float* c, const uint32_t* a, uint32_t b0, uint32_t b1) {
    asm volatile("mma.sync.aligned.m16n8k16.row.col.f32.bf16.bf16.f32 "
        "{%0,%1,%2,%3}, {%4,%5,%6,%7}, {%8,%9}, {%0,%1,%2,%3};"
        : "+f"(c[0]), "+f"(c[1]), "+f"(c[2]), "+f"(c[3])
        : "r"(a[0]), "r"(a[1]), "r"(a[2]), "r"(a[3]), "r"(b0), "r"(b1));
}
// build hi+lo bf16x2 frags from a float2 (exact split)
__device__ __forceinline__ void split2(float2 v, uint32_t& hi, uint32_t& lo) {
    hi = packbf(v.x, v.y);
    float hx = __uint_as_float(hi << 16);
    float hy = __uint_as_float(hi & 0xFFFF0000u);
    lo = packbf(v.x - hx, v.y - hy);
}

// ---------------- kernel 0: W2/W3 -> transposed bf16 hi/lo blob ----------------
__global__ __launch_bounds__(256) void prep_w_kernel(const float* __restrict__ ew2,
                                                     const float* __restrict__ ew3)
{
    const float* W = blockIdx.x ? ew3 : ew2;
    __nv_bfloat16* dh = g_WT + (size_t)blockIdx.x * 2 * 128 * WPITCH;
    __nv_bfloat16* dl = dh + 128 * WPITCH;
    for (int idx = threadIdx.x; idx < 128 * 64; idx += 256) {
        int n = idx >> 6, kp = idx & 63, k = kp * 2;
        float2 v = make_float2(W[k * 128 + n], W[(k + 1) * 128 + n]);
        uint32_t hi, lo;
        split2(v, hi, lo);
        *(uint32_t*)((char*)dh + n * (WPITCH * 2) + k * 2) = hi;
        *(uint32_t*)((char*)dl + n * (WPITCH * 2) + k * 2) = lo;
    }
}

// ---------------- kernel 1: per-node features + A/B projections ----------------
__global__ __launch_bounds__(128) void prep_node_kernel(
    const float* __restrict__ atom10, const int* __restrict__ seq_idx,
    const float* __restrict__ t, const float* __restrict__ fixed_mask,
    const float* __restrict__ sc_trans, const float* __restrict__ sc_rots,
    const float* __restrict__ sc_atom14, const float* __restrict__ ew1)
{
    __shared__ float pt[73];
    __shared__ float nin[NODE_IN];
    const int row = blockIdx.x;
    const int b = row / NRES;
    const int tid = threadIdx.x;

    if (tid < 16) {
        float fr = expf((float)tid * (-logf(10000.0f) / 15.0f));
        float ang = t[b] * 10000.0f * fr;
        pt[tid]      = sinf(ang);
        pt[16 + tid] = cosf(ang);
        float den = powf(2056.0f, (float)tid / 16.0f);
        float ang2 = (float)seq_idx[row] * PI_F / den;
        nin[73 + tid]      = sinf(ang2);
        nin[73 + 16 + tid] = cosf(ang2);
    }
    if (tid == 0) pt[32] = fixed_mask[row];
    if (tid < 30) pt[33 + tid] = atom10[row * 30 + tid];
    if (tid < 10) {
        const float* ap = atom10 + row * 30 + tid * 3;
        float x = ap[0], y = ap[1], z = ap[2];
        float d = sqrtf(x * x + y * y + z * z);
        pt[63 + tid] = 1.0f / (1.0f + d * d);
        const float* tr = sc_trans + row * 3;
        const float* R  = sc_rots  + row * 9;
        const float* at = sc_atom14 + row * 42 + (4 + tid) * 3;
        float d0 = at[0] - tr[0], d1 = at[1] - tr[1], d2 = at[2] - tr[2];
        float l0 = d0 * R[0] + d1 * R[3] + d2 * R[6];
        float l1 = d0 * R[1] + d1 * R[4] + d2 * R[7];
        float l2 = d0 * R[2] + d1 * R[5] + d2 * R[8];
        nin[105 + tid * 3 + 0] = l0;
        nin[105 + tid * 3 + 1] = l1;
        nin[105 + tid * 3 + 2] = l2;
        float ld = sqrtf(l0 * l0 + l1 * l1 + l2 * l2);
        nin[135 + tid] = 1.0f / (1.0f + ld);
    }
    __syncthreads();
    if (tid < 73) nin[tid] = pt[tid];
    __syncthreads();

    for (int x = tid; x < NODE_IN; x += 128)
        g_NIN[row * NODE_IN + x] = nin[x];

    if (tid < CZ) {
        float accA = 0.f, accB = 0.f;
        #pragma unroll 4
        for (int f = 0; f < 73; f++) {
            float p = pt[f];
            accA = fmaf(p, ew1[f * CZ + tid], accA);
            accB = fmaf(p, ew1[(73 + f) * CZ + tid], accB);
        }
        g_NA[row * CZ + tid] = accA;
        g_NB[row * CZ + tid] = accB;
    }
}

// ---------------- kernel 2: relative-position table ----------------
__global__ __launch_bounds__(128) void prep_rel_kernel(const float* __restrict__ ew1)
{
    __shared__ float emb[32];
    const int r = blockIdx.x;
    const int tid = threadIdx.x;
    if (tid < 16) {
        float v = (float)(r - 383);
        float den = powf(2056.0f, (float)tid / 16.0f);
        float ang = v * PI_F / den;
        emb[tid]      = sinf(ang);
        emb[16 + tid] = cosf(ang);
    }
    __syncthreads();
    float acc = 0.f;
    #pragma unroll
    for (int k = 0; k < 32; k++)
        acc = fmaf(emb[k], ew1[(146 + k) * CZ + tid], acc);
    g_REL[r * CZ + tid] = acc;
}

// ---------------- kernel 3: node MLP + LN (8 rows/CTA) ----------------
__global__ __launch_bounds__(256) void node_mlp_kernel(
    const float* __restrict__ nw1, const float* __restrict__ nb1,
    const float* __restrict__ nw2, const float* __restrict__ nb2,
    const float* __restrict__ nw3, const float* __restrict__ nb3,
    const float* __restrict__ ng,  const float* __restrict__ nbt,
    float* __restrict__ outN)
{
    __shared__ float nin[NROWS][NODE_IN];
    __shared__ float h[NROWS][CS];
    __shared__ float sred[NROWS][8], s2red[NROWS][8];
    const int r0 = blockIdx.x * NROWS;
    const int tid = threadIdx.x;

    for (int x = tid; x < NROWS * NODE_IN; x += 256)
        nin[x / NODE_IN][x % NODE_IN] = g_NIN[r0 * NODE_IN + x];
    __syncthreads();

    float a[NROWS];
    #pragma unroll
    for (int r = 0; r < NROWS; r++) a[r] = nb1[tid];
    #pragma unroll 4
    for (int k = 0; k < NODE_IN; k++) {
        float w = nw1[k * CS + tid];
        #pragma unroll
        for (int r = 0; r < NROWS; r++) a[r] = fmaf(nin[r][k], w, a[r]);
    }
    #pragma unroll
    for (int r = 0; r < NROWS; r++) h[r][tid] = fmaxf(a[r], 0.f);
    __syncthreads();

    #pragma unroll
    for (int r = 0; r < NROWS; r++) a[r] = nb2[tid];
    #pragma unroll 4
    for (int k = 0; k < CS; k++) {
        float w = nw2[k * CS + tid];
        #pragma unroll
        for (int r = 0; r < NROWS; r++) a[r] = fmaf(h[r][k], w, a[r]);
    }
    __syncthreads();
    #pragma unroll
    for (int r = 0; r < NROWS; r++) h[r][tid] = fmaxf(a[r], 0.f);
    __syncthreads();

    #pragma unroll
    for (int r = 0; r < NROWS; r++) a[r] = nb3[tid];
    #pragma unroll 4
    for (int k = 0; k < CS; k++) {
        float w = nw3[k * CS + tid];
        #pragma unroll
        for (int r = 0; r < NROWS; r++) a[r] = fmaf(h[r][k], w, a[r]);
    }

    #pragma unroll
    for (int r = 0; r < NROWS; r++) {
        float s = a[r], s2 = a[r] * a[r];
        #pragma unroll
        for (int o = 16; o > 0; o >>= 1) {
            s  += __shfl_xor_sync(0xffffffffu, s,  o);
            s2 += __shfl_xor_sync(0xffffffffu, s2, o);
        }
        if ((tid & 31) == 0) { sred[r][tid >> 5] = s; s2red[r][tid >> 5] = s2; }
    }
    __syncthreads();
    float gv = ng[tid], bv = nbt[tid];
    #pragma unroll
    for (int r = 0; r < NROWS; r++) {
        float S = 0.f, S2 = 0.f;
        #pragma unroll
        for (int w = 0; w < 8; w++) { S += sred[r][w]; S2 += s2red[r][w]; }
        float mu = S * (1.0f / CS);
        float var = S2 * (1.0f / CS) - mu * mu;
        float rs = rsqrtf(var + 1e-5f);
        outN[(r0 + r) * CS + tid] = (a[r] - mu) * rs * gv + bv;
    }
}

// ---------------- kernel 4: edge MLP via mma.sync bf16 3-pass split ----------------
__global__ __launch_bounds__(256) void edge_kernel_mma(
    const int* __restrict__ seq_idx, const float* __restrict__ sc_trans,
    const float* __restrict__ ew1, const float* __restrict__ eb1,
    const float* __restrict__ eb2, const float* __restrict__ eb3,
    const float* __restrict__ eg,  const float* __restrict__ ebt,
    float* __restrict__ outE)
{
    extern __shared__ char smx[];
    float* baseS = (float*)(smx + SM_AUX);
    float* eb2s  = baseS + 128;
    float* eb3s  = eb2s + 128;
    float* egs   = eb3s + 128;
    float* ebts  = egs  + 128;
    int*   relS  = (int*)(ebts + 128);
    int*   binS  = relS + 128;

    const int jt = blockIdx.x, i = blockIdx.y, b = blockIdx.z;
    const int j0 = jt * 128;
    const int tid = threadIdx.x;
    const int w = tid >> 5, lane = tid & 31, g = lane >> 2, tg = lane & 3;
    const int row_i = b * NRES + i;

    // linear copy of pre-split transposed weights (W2h|W2l|W3h|W3l)
    {
        const uint4* src = (const uint4*)g_WT;
        uint4* dst = (uint4*)smx;
        for (int x = tid; x < (4 * WTILE_B) / 16; x += 256) dst[x] = src[x];
    }
    if (tid < 128) {
        baseS[tid] = g_NA[row_i * CZ + tid] + eb1[tid];
        eb2s[tid] = eb2[tid]; eb3s[tid] = eb3[tid];
        egs[tid]  = eg[tid];  ebts[tid] = ebt[tid];
    } else {
        const int m = tid - 128;
        const int row_j = b * NRES + j0 + m;
        int r = seq_idx[row_i] - seq_idx[row_j] + 383;
        relS[m] = min(max(r, 0), 766);
        float dx = sc_trans[row_i * 3 + 0] - sc_trans[row_j * 3 + 0];
        float dy = sc_trans[row_i * 3 + 1] - sc_trans[row_j * 3 + 1];
        float dz = sc_trans[row_i * 3 + 2] - sc_trans[row_j * 3 + 2];
        float d = sqrtf(dx * dx + dy * dy + dz * dz);
        int bin = -1;
        const double step = (20.0 - 1e-05) / 21.0;
        #pragma unroll
        for (int k = 0; k < 22; k++) {
            float lo = (float)(1e-05 + k * step);
            float hi = (k < 21) ? (float)(1e-05 + (k + 1) * step) : 1e8f;
            if (d > lo && d < hi) bin = k;
        }
        binS[m] = bin;
    }
    __syncthreads();

    // stage h1 = relu(base + NB + REL + dgram) into smem [128][H1PITCH]
    float* H1 = (float*)(smx + SM_H1);
    {
        const int k = tid & 127;
        const int half = tid >> 7;
        #pragma unroll 4
        for (int it = 0; it < 64; it++) {
            const int m = it * 2 + half;
            float v = baseS[k] + g_NB[((size_t)(b * NRES + j0 + m)) * CZ + k]
                    + g_REL[(size_t)relS[m] * CZ + k];
            int bin = binS[m];
            if (bin >= 0) v += ew1[(178 + bin) * CZ + k];
            H1[m * H1PITCH + k] = fmaxf(v, 0.f);
        }
    }
    __syncthreads();
    // ---------- from here, fully warp-synchronous ----------

    const int rA = 16 * w + g;                // this thread's first m-row
    // A1 fragments (h1) hi/lo
    uint32_t A1h[8][4], A1l[8][4];
    #pragma unroll
    for (int kt = 0; kt < 8; kt++) {
        const int c0 = kt * 16 + 2 * tg;
        float2 vA0 = *(const float2*)&H1[rA * H1PITCH + c0];
        float2 vA1 = *(const float2*)&H1[rA * H1PITCH + c0 + 8];
        float2 vB0 = *(const float2*)&H1[(rA + 8) * H1PITCH + c0];
        float2 vB1 = *(const float2*)&H1[(rA + 8) * H1PITCH + c0 + 8];
        split2(vA0, A1h[kt][0], A1l[kt][0]);
        split2(vB0, A1h[kt][1], A1l[kt][1]);
        split2(vA1, A1h[kt][2], A1l[kt][2]);
        split2(vB1, A1h[kt][3], A1l[kt][3]);
    }

    float acc[16][4];
    #pragma unroll
    for (int nt = 0; nt < 16; nt++)
        #pragma unroll
        for (int c = 0; c < 4; c++) acc[nt][c] = 0.f;

    // ---- GEMM 1: h1 @ W2, 3-pass split ----
    #pragma unroll
    for (int kt = 0; kt < 8; kt++) {
        const int koff = (kt * 16 + 2 * tg) * 2;
        #pragma unroll
        for (int nt = 0; nt < 16; nt++) {
            const int roff = (nt * 8 + g) * (WPITCH * 2);
            uint32_t b0h = *(const uint32_t*)(smx + SM_W2H + roff + koff);
            uint32_t b1h = *(const uint32_t*)(smx + SM_W2H + roff + koff + 16);
            uint32_t b0l = *(const uint32_t*)(smx + SM_W2L + roff + koff);
            uint32_t b1l = *(const uint32_t*)(smx + SM_W2L + roff + koff + 16);
            mma16816(acc[nt], A1h[kt], b0h, b1h);
            mma16816(acc[nt], A1h[kt], b0l, b1l);
            mma16816(acc[nt], A1l[kt], b0h, b1h);
        }
    }

    // epilogue 1: bias + relu, convert C-frags -> A2-frags (register chain)
    uint32_t A2h[8][4], A2l[8][4];
    #pragma unroll
    for (int nt = 0; nt < 16; nt++) {
        float2 bb = *(const float2*)&eb2s[nt * 8 + 2 * tg];
        acc[nt][0] = fmaxf(acc[nt][0] + bb.x, 0.f);
        acc[nt][1] = fmaxf(acc[nt][1] + bb.y, 0.f);
        acc[nt][2] = fmaxf(acc[nt][2] + bb.x, 0.f);
        acc[nt][3] = fmaxf(acc[nt][3] + bb.y, 0.f);
    }
    #pragma unroll
    for (int kt = 0; kt < 8; kt++) {
        split2(make_float2(acc[2*kt][0],   acc[2*kt][1]),   A2h[kt][0], A2l[kt][0]);
        split2(make_float2(acc[2*kt][2],   acc[2*kt][3]),   A2h[kt][1], A2l[kt][1]);
        split2(make_float2(acc[2*kt+1][0], acc[2*kt+1][1]), A2h[kt][2], A2l[kt][2]);
        split2(make_float2(acc[2*kt+1][2], acc[2*kt+1][3]), A2h[kt][3], A2l[kt][3]);
    }
    #pragma unroll
    for (int nt = 0; nt < 16; nt++)
        #pragma unroll
        for (int c = 0; c < 4; c++) acc[nt][c] = 0.f;

    // ---- GEMM 2: h2 @ W3, 3-pass split ----
    #pragma unroll
    for (int kt = 0; kt < 8; kt++) {
        const int koff = (kt * 16 + 2 * tg) * 2;
        #pragma unroll
        for (int nt = 0; nt < 16; nt++) {
            const int roff = (nt * 8 + g) * (WPITCH * 2);
            uint32_t b0h = *(const uint32_t*)(smx + SM_W3H + roff + koff);
            uint32_t b1h = *(const uint32_t*)(smx + SM_W3H + roff + koff + 16);
            uint32_t b0l = *(const uint32_t*)(smx + SM_W3L + roff + koff);
            uint32_t b1l = *(const uint32_t*)(smx + SM_W3L + roff + koff + 16);
            mma16816(acc[nt], A2h[kt], b0h, b1h);
            mma16816(acc[nt], A2h[kt], b0l, b1l);
            mma16816(acc[nt], A2l[kt], b0h, b1h);
        }
    }

    // epilogue 2: bias3, LayerNorm over n (quad reduction), store
    float sA = 0.f, s2A = 0.f, sB = 0.f, s2B = 0.f;
    #pragma unroll
    for (int nt = 0; nt < 16; nt++) {
        float2 bb = *(const float2*)&eb3s[nt * 8 + 2 * tg];
        acc[nt][0] += bb.x; acc[nt][1] += bb.y;
        acc[nt][2] += bb.x; acc[nt][3] += bb.y;
        sA += acc[nt][0] + acc[nt][1]; s2A += acc[nt][0]*acc[nt][0] + acc[nt][1]*acc[nt][1];
        sB += acc[nt][2] + acc[nt][3]; s2B += acc[nt][2]*acc[nt][2] + acc[nt][3]*acc[nt][3];
    }
    #pragma unroll
    for (int o = 1; o <= 2; o <<= 1) {
        sA  += __shfl_xor_sync(0xffffffffu, sA,  o);
        s2A += __shfl_xor_sync(0xffffffffu, s2A, o);
        sB  += __shfl_xor_sync(0xffffffffu, sB,  o);
        s2B += __shfl_xor_sync(0xffffffffu, s2B, o);
    }
    float muA = sA * (1.0f/128.0f), vA = s2A * (1.0f/128.0f) - muA*muA;
    float muB = sB * (1.0f/128.0f), vB = s2B * (1.0f/128.0f) - muB*muB;
    float rsA = rsqrtf(vA + 1e-5f), rsB = rsqrtf(vB + 1e-5f);

    float* opA = outE + (((size_t)(b * NRES + i)) * NRES + j0 + rA) * CZ;
    float* opB = opA + 8 * CZ;
    #pragma unroll
    for (int nt = 0; nt < 16; nt++) {
        const int col = nt * 8 + 2 * tg;
        float2 gg = *(const float2*)&egs[col];
        float2 bb = *(const float2*)&ebts[col];
        float2 o0, o1;
        o0.x = (acc[nt][0] - muA) * rsA * gg.x + bb.x;
        o0.y = (acc[nt][1] - muA) * rsA * gg.y + bb.y;
        o1.x = (acc[nt][2] - muB) * rsB * gg.x + bb.x;
        o1.y = (acc[nt][3] - muB) * rsB * gg.y + bb.y;
        *(float2*)(opA + col) = o0;
        *(float2*)(opB + col) = o1;
    }
}

// ---------------- launch ----------------
extern "C" void kernel_launch(void* const* d_in, const int* in_sizes, int n_in,
                              void* d_out, int out_size)
{
    const float* atom10     = (const float*)d_in[0];
    const int*   seq_idx    = (const int*)  d_in[1];
    const float* t          = (const float*)d_in[2];
    const float* fixed_mask = (const float*)d_in[3];
    /* d_in[4] node_mask unused */
    const float* sc_trans   = (const float*)d_in[5];
    const float* sc_rots    = (const float*)d_in[6];
    const float* sc_atom14  = (const float*)d_in[7];
    const float* nw1 = (const float*)d_in[8];
    const float* nb1 = (const float*)d_in[9];
    const float* nw2 = (const float*)d_in[10];
    const float* nb2 = (const float*)d_in[11];
    const float* nw3 = (const float*)d_in[12];
    const float* nb3 = (const float*)d_in[13];
    const float* ng  = (const float*)d_in[14];
    const float* nbt = (const float*)d_in[15];
    const float* ew1 = (const float*)d_in[16];
    const float* eb1 = (const float*)d_in[17];
    const float* ew2 = (const float*)d_in[18];
    const float* eb2 = (const float*)d_in[19];
    const float* ew3 = (const float*)d_in[20];
    const float* eb3 = (const float*)d_in[21];
    const float* eg  = (const float*)d_in[22];
    const float* ebt = (const float*)d_in[23];

    float* outN = (float*)d_out;
    float* outE = outN + (size_t)BB * NRES * CS;   // node first, then edge

    cudaFuncSetAttribute(edge_kernel_mma, cudaFuncAttributeMaxDynamicSharedMemorySize,
                         SMEM_TOTAL);

    prep_w_kernel<<<2, 256>>>(ew2, ew3);
    prep_node_kernel<<<BB * NRES, 128>>>(atom10, seq_idx, t, fixed_mask,
                                         sc_trans, sc_rots, sc_atom14, ew1);
    prep_rel_kernel<<<767, 128>>>(ew1);
    node_mlp_kernel<<<BB * NRES / NROWS, 256>>>(nw1, nb1, nw2, nb2, nw3, nb3, ng, nbt, outN);
    edge_kernel_mma<<<dim3(NRES / 128, NRES, BB), 256, SMEM_TOTAL>>>(
        seq_idx, sc_trans, ew1, eb1, eb2, eb3, eg, ebt, outE);
}

// round 10
// speedup vs baseline: 1.6469x; 1.1919x over previous
#include <cuda_runtime.h>
#include <cuda_bf16.h>
#include <math.h>
#include <stdint.h>

#define BB 2
#define NRES 384
#define CS 256
#define CZ 128
#define NODE_IN 145
#define NROWS 16
#define PI_F 3.14159265358979323846f

// quad layout: quad(kt, idx, tg) holds bf16 elems k = kt*16+2tg, +1, +8, +9 for row idx
// byte addr = base + kt*QKT + idx*32 + tg*8   (QKT=4128 keeps kt blocks bank-staggered)
#define QKT 4128
#define WTILE 33024               // 8 * QKT

// smem byte offsets (edge kernel)
#define SM_W2H 0
#define SM_W2L 33024
#define SM_W3H 66048
#define SM_W3L 99072
#define SM_AH  132096
#define SM_AL  165120
#define SM_AUX 198144
#define SMEM_TOTAL (SM_AUX + 5632)

// ---------------- scratch (no allocation allowed) ----------------
__device__ float g_NIN[BB * NRES * NODE_IN];
__device__ float g_NA [BB * NRES * CZ];
__device__ float g_NB [BB * NRES * CZ];
__device__ float g_REL[767 * CZ];
__device__ __align__(16) unsigned char g_WT[4 * WTILE];   // W2h | W2l | W3h | W3l in quad layout

// ---------------- helpers ----------------
__device__ __forceinline__ uint32_t packbf(float lo, float hi) {
    uint32_t r;
    asm("cvt.rn.bf16x2.f32 %0, %1, %2;" : "=r"(r) : "f"(hi), "f"(lo));
    return r;
}
__device__ __forceinline__ void mma16816(float* c, const uint32_t* a, uint32_t b0, uint32_t b1) {
    asm volatile("mma.sync.aligned.m16n8k16.row.col.f32.bf16.bf16.f32 "
        "{%0,%1,%2,%3}, {%4,%5,%6,%7}, {%8,%9}, {%0,%1,%2,%3};"
        : "+f"(c[0]), "+f"(c[1]), "+f"(c[2]), "+f"(c[3])
        : "r"(a[0]), "r"(a[1]), "r"(a[2]), "r"(a[3]), "r"(b0), "r"(b1));
}
__device__ __forceinline__ void split2(float2 v, uint32_t& hi, uint32_t& lo) {
    hi = packbf(v.x, v.y);
    float hx = __uint_as_float(hi << 16);
    float hy = __uint_as_float(hi & 0xFFFF0000u);
    lo = packbf(v.x - hx, v.y - hy);
}

// ---------------- kernel 0: W2/W3 -> quad-layout bf16 hi/lo blob ----------------
__global__ __launch_bounds__(256) void prep_w_kernel(const float* __restrict__ ew2,
                                                     const float* __restrict__ ew3)
{
    const float* W = blockIdx.x ? ew3 : ew2;
    unsigned char* dh = g_WT + (size_t)blockIdx.x * 2 * WTILE;
    unsigned char* dl = dh + WTILE;
    for (int q = threadIdx.x; q < 8 * 128 * 4; q += 256) {
        int kt = q >> 9, rem = q & 511, n = rem >> 2, tg = rem & 3;
        int k0 = kt * 16 + 2 * tg;
        float2 va = make_float2(W[k0 * 128 + n], W[(k0 + 1) * 128 + n]);
        float2 vb = make_float2(W[(k0 + 8) * 128 + n], W[(k0 + 9) * 128 + n]);
        uint32_t ha, la, hb, lb;
        split2(va, ha, la);
        split2(vb, hb, lb);
        uint32_t off = kt * QKT + n * 32 + tg * 8;
        *(uint2*)(dh + off) = make_uint2(ha, hb);
        *(uint2*)(dl + off) = make_uint2(la, lb);
    }
}

// ---------------- kernel 1: per-node features + A/B projections ----------------
__global__ __launch_bounds__(128) void prep_node_kernel(
    const float* __restrict__ atom10, const int* __restrict__ seq_idx,
    const float* __restrict__ t, const float* __restrict__ fixed_mask,
    const float* __restrict__ sc_trans, const float* __restrict__ sc_rots,
    const float* __restrict__ sc_atom14, const float* __restrict__ ew1)
{
    __shared__ float pt[73];
    __shared__ float nin[NODE_IN];
    const int row = blockIdx.x;
    const int b = row / NRES;
    const int tid = threadIdx.x;

    if (tid < 16) {
        float fr = expf((float)tid * (-logf(10000.0f) / 15.0f));
        float ang = t[b] * 10000.0f * fr;
        pt[tid]      = sinf(ang);
        pt[16 + tid] = cosf(ang);
        float den = powf(2056.0f, (float)tid / 16.0f);
        float ang2 = (float)seq_idx[row] * PI_F / den;
        nin[73 + tid]      = sinf(ang2);
        nin[73 + 16 + tid] = cosf(ang2);
    }
    if (tid == 0) pt[32] = fixed_mask[row];
    if (tid < 30) pt[33 + tid] = atom10[row * 30 + tid];
    if (tid < 10) {
        const float* ap = atom10 + row * 30 + tid * 3;
        float x = ap[0], y = ap[1], z = ap[2];
        float d = sqrtf(x * x + y * y + z * z);
        pt[63 + tid] = 1.0f / (1.0f + d * d);
        const float* tr = sc_trans + row * 3;
        const float* R  = sc_rots  + row * 9;
        const float* at = sc_atom14 + row * 42 + (4 + tid) * 3;
        float d0 = at[0] - tr[0], d1 = at[1] - tr[1], d2 = at[2] - tr[2];
        float l0 = d0 * R[0] + d1 * R[3] + d2 * R[6];
        float l1 = d0 * R[1] + d1 * R[4] + d2 * R[7];
        float l2 = d0 * R[2] + d1 * R[5] + d2 * R[8];
        nin[105 + tid * 3 + 0] = l0;
        nin[105 + tid * 3 + 1] = l1;
        nin[105 + tid * 3 + 2] = l2;
        float ld = sqrtf(l0 * l0 + l1 * l1 + l2 * l2);
        nin[135 + tid] = 1.0f / (1.0f + ld);
    }
    __syncthreads();
    if (tid < 73) nin[tid] = pt[tid];
    __syncthreads();

    for (int x = tid; x < NODE_IN; x += 128)
        g_NIN[row * NODE_IN + x] = nin[x];

    if (tid < CZ) {
        float accA = 0.f, accB = 0.f;
        #pragma unroll 4
        for (int f = 0; f < 73; f++) {
            float p = pt[f];
            accA = fmaf(p, ew1[f * CZ + tid], accA);
            accB = fmaf(p, ew1[(73 + f) * CZ + tid], accB);
        }
        g_NA[row * CZ + tid] = accA;
        g_NB[row * CZ + tid] = accB;
    }
}

// ---------------- kernel 2: relative-position table ----------------
__global__ __launch_bounds__(128) void prep_rel_kernel(const float* __restrict__ ew1)
{
    __shared__ float emb[32];
    const int r = blockIdx.x;
    const int tid = threadIdx.x;
    if (tid < 16) {
        float v = (float)(r - 383);
        float den = powf(2056.0f, (float)tid / 16.0f);
        float ang = v * PI_F / den;
        emb[tid]      = sinf(ang);
        emb[16 + tid] = cosf(ang);
    }
    __syncthreads();
    float acc = 0.f;
    #pragma unroll
    for (int k = 0; k < 32; k++)
        acc = fmaf(emb[k], ew1[(146 + k) * CZ + tid], acc);
    g_REL[r * CZ + tid] = acc;
}

// ---------------- kernel 3: node MLP + LN (16 rows/CTA) ----------------
__global__ __launch_bounds__(256) void node_mlp_kernel(
    const float* __restrict__ nw1, const float* __restrict__ nb1,
    const float* __restrict__ nw2, const float* __restrict__ nb2,
    const float* __restrict__ nw3, const float* __restrict__ nb3,
    const float* __restrict__ ng,  const float* __restrict__ nbt,
    float* __restrict__ outN)
{
    __shared__ float nin[NROWS][NODE_IN];
    __shared__ float h[NROWS][CS];
    __shared__ float sred[NROWS][8], s2red[NROWS][8];
    const int r0 = blockIdx.x * NROWS;
    const int tid = threadIdx.x;

    for (int x = tid; x < NROWS * NODE_IN; x += 256)
        nin[x / NODE_IN][x % NODE_IN] = g_NIN[r0 * NODE_IN + x];
    __syncthreads();

    float a[NROWS];
    #pragma unroll
    for (int r = 0; r < NROWS; r++) a[r] = nb1[tid];
    #pragma unroll 8
    for (int k = 0; k < NODE_IN; k++) {
        float w = nw1[k * CS + tid];
        #pragma unroll
        for (int r = 0; r < NROWS; r++) a[r] = fmaf(nin[r][k], w, a[r]);
    }
    #pragma unroll
    for (int r = 0; r < NROWS; r++) h[r][tid] = fmaxf(a[r], 0.f);
    __syncthreads();

    #pragma unroll
    for (int r = 0; r < NROWS; r++) a[r] = nb2[tid];
    #pragma unroll 8
    for (int k = 0; k < CS; k++) {
        float w = nw2[k * CS + tid];
        #pragma unroll
        for (int r = 0; r < NROWS; r++) a[r] = fmaf(h[r][k], w, a[r]);
    }
    __syncthreads();
    #pragma unroll
    for (int r = 0; r < NROWS; r++) h[r][tid] = fmaxf(a[r], 0.f);
    __syncthreads();

    #pragma unroll
    for (int r = 0; r < NROWS; r++) a[r] = nb3[tid];
    #pragma unroll 8
    for (int k = 0; k < CS; k++) {
        float w = nw3[k * CS + tid];
        #pragma unroll
        for (int r = 0; r < NROWS; r++) a[r] = fmaf(h[r][k], w, a[r]);
    }

    #pragma unroll
    for (int r = 0; r < NROWS; r++) {
        float s = a[r], s2 = a[r] * a[r];
        #pragma unroll
        for (int o = 16; o > 0; o >>= 1) {
            s  += __shfl_xor_sync(0xffffffffu, s,  o);
            s2 += __shfl_xor_sync(0xffffffffu, s2, o);
        }
        if ((tid & 31) == 0) { sred[r][tid >> 5] = s; s2red[r][tid >> 5] = s2; }
    }
    __syncthreads();
    float gv = ng[tid], bv = nbt[tid];
    #pragma unroll
    for (int r = 0; r < NROWS; r++) {
        float S = 0.f, S2 = 0.f;
        #pragma unroll
        for (int w = 0; w < 8; w++) { S += sred[r][w]; S2 += s2red[r][w]; }
        float mu = S * (1.0f / CS);
        float var = S2 * (1.0f / CS) - mu * mu;
        float rs = rsqrtf(var + 1e-5f);
        outN[(r0 + r) * CS + tid] = (a[r] - mu) * rs * gv + bv;
    }
}

// ---------------- kernel 4: edge MLP, 16 warps, quad-layout mma.sync ----------------
__global__ __launch_bounds__(512) void edge_kernel_mma(
    const int* __restrict__ seq_idx, const float* __restrict__ sc_trans,
    const float* __restrict__ ew1, const float* __restrict__ eb1,
    const float* __restrict__ eb2, const float* __restrict__ eb3,
    const float* __restrict__ eg,  const float* __restrict__ ebt,
    float* __restrict__ outE)
{
    extern __shared__ char smx[];
    float* baseS = (float*)(smx + SM_AUX);
    float* eb2s  = baseS + 128;
    float* eb3s  = eb2s + 128;
    float* egs   = eb3s + 128;
    float* ebts  = egs  + 128;
    int*   relS  = (int*)(ebts + 128);
    int*   binS  = relS + 128;
    float2* part = (float2*)(binS + 128);   // [half][row] partial (sum, sum2), 2*128

    const int jt = blockIdx.x, i = blockIdx.y, b = blockIdx.z;
    const int j0 = jt * 128;
    const int tid = threadIdx.x;
    const int w = tid >> 5, lane = tid & 31, g = lane >> 2, tg = lane & 3;
    const int row_i = b * NRES + i;

    // weights -> smem (linear copy, quad layout preserved)
    {
        const uint4* src = (const uint4*)g_WT;
        uint4* dst = (uint4*)smx;
        for (int x = tid; x < (4 * WTILE) / 16; x += 512) dst[x] = src[x];
    }
    if (tid < 128) {
        baseS[tid] = g_NA[row_i * CZ + tid] + eb1[tid];
        eb2s[tid] = eb2[tid]; eb3s[tid] = eb3[tid];
        egs[tid]  = eg[tid];  ebts[tid] = ebt[tid];
    } else if (tid < 256) {
        const int m = tid - 128;
        const int row_j = b * NRES + j0 + m;
        int r = seq_idx[row_i] - seq_idx[row_j] + 383;
        relS[m] = min(max(r, 0), 766);
        float dx = sc_trans[row_i * 3 + 0] - sc_trans[row_j * 3 + 0];
        float dy = sc_trans[row_i * 3 + 1] - sc_trans[row_j * 3 + 1];
        float dz = sc_trans[row_i * 3 + 2] - sc_trans[row_j * 3 + 2];
        float d = sqrtf(dx * dx + dy * dy + dz * dz);
        int bin = -1;
        const double step = (20.0 - 1e-05) / 21.0;
        #pragma unroll
        for (int k = 0; k < 22; k++) {
            float lo = (float)(1e-05 + k * step);
            float hi = (k < 21) ? (float)(1e-05 + (k + 1) * step) : 1e8f;
            if (d > lo && d < hi) bin = k;
        }
        binS[m] = bin;
    }
    __syncthreads();

    // build A1 quads directly: h1[m][k] = relu(base + NB + REL + dgram), split hi/lo
    {
        const int kt = lane >> 2;       // 0..7
        const int k0 = kt * 16 + 2 * tg;
        #pragma unroll
        for (int p = 0; p < 8; p++) {
            const int m = w * 8 + p;
            const int rel = relS[m], bin = binS[m];
            const float* nb = g_NB + ((size_t)(b * NRES + j0 + m)) * CZ;
            const float* rl = g_REL + (size_t)rel * CZ;
            float2 va = make_float2(baseS[k0] + nb[k0] + rl[k0],
                                    baseS[k0 + 1] + nb[k0 + 1] + rl[k0 + 1]);
            float2 vb = make_float2(baseS[k0 + 8] + nb[k0 + 8] + rl[k0 + 8],
                                    baseS[k0 + 9] + nb[k0 + 9] + rl[k0 + 9]);
            if (bin >= 0) {
                const float* dg = ew1 + (178 + bin) * CZ;
                va.x += dg[k0];     va.y += dg[k0 + 1];
                vb.x += dg[k0 + 8]; vb.y += dg[k0 + 9];
            }
            va.x = fmaxf(va.x, 0.f); va.y = fmaxf(va.y, 0.f);
            vb.x = fmaxf(vb.x, 0.f); vb.y = fmaxf(vb.y, 0.f);
            uint32_t ha, la, hb, lb;
            split2(va, ha, la);
            split2(vb, hb, lb);
            const uint32_t off = kt * QKT + m * 32 + tg * 8;
            *(uint2*)(smx + SM_AH + off) = make_uint2(ha, hb);
            *(uint2*)(smx + SM_AL + off) = make_uint2(la, lb);
        }
    }
    __syncthreads();

    const int mt = w & 7, half = w >> 3, nts = half * 8;
    const int rA = mt * 16 + g;

    float acc[8][4];
    #pragma unroll
    for (int nt = 0; nt < 8; nt++)
        #pragma unroll
        for (int c = 0; c < 4; c++) acc[nt][c] = 0.f;

    // ---- GEMM 1 ----
    #pragma unroll
    for (int kt = 0; kt < 8; kt++) {
        const uint32_t aoff = kt * QKT + tg * 8;
        uint2 qah = *(const uint2*)(smx + SM_AH + aoff + rA * 32);
        uint2 qbh = *(const uint2*)(smx + SM_AH + aoff + (rA + 8) * 32);
        uint2 qal = *(const uint2*)(smx + SM_AL + aoff + rA * 32);
        uint2 qbl = *(const uint2*)(smx + SM_AL + aoff + (rA + 8) * 32);
        uint32_t ah[4] = { qah.x, qbh.x, qah.y, qbh.y };
        uint32_t al[4] = { qal.x, qbl.x, qal.y, qbl.y };
        #pragma unroll
        for (int nt = 0; nt < 8; nt++) {
            const int n = (nts + nt) * 8 + g;
            const uint32_t boff = kt * QKT + n * 32 + tg * 8;
            uint2 wh = *(const uint2*)(smx + SM_W2H + boff);
            uint2 wl = *(const uint2*)(smx + SM_W2L + boff);
            mma16816(acc[nt], ah, wh.x, wh.y);
            mma16816(acc[nt], ah, wl.x, wl.y);
            mma16816(acc[nt], al, wh.x, wh.y);
        }
    }
    __syncthreads();   // all warps done reading A1 before A2 overwrites

    // epilogue 1: bias + relu -> A2 quads (hi/lo) back into A buffer
    #pragma unroll
    for (int nt = 0; nt < 8; nt++) {
        const int cg = nts + nt;
        const int c0 = cg * 8 + 2 * tg;
        float b0f = eb2s[c0], b1f = eb2s[c0 + 1];
        float2 vA = make_float2(fmaxf(acc[nt][0] + b0f, 0.f), fmaxf(acc[nt][1] + b1f, 0.f));
        float2 vB = make_float2(fmaxf(acc[nt][2] + b0f, 0.f), fmaxf(acc[nt][3] + b1f, 0.f));
        uint32_t hA, lA, hB, lB;
        split2(vA, hA, lA);
        split2(vB, hB, lB);
        const int kt2 = cg >> 1;
        const int off4 = (cg & 1) * 4;
        const uint32_t oA = kt2 * QKT + rA * 32 + tg * 8 + off4;
        const uint32_t oB = kt2 * QKT + (rA + 8) * 32 + tg * 8 + off4;
        *(uint32_t*)(smx + SM_AH + oA) = hA;
        *(uint32_t*)(smx + SM_AH + oB) = hB;
        *(uint32_t*)(smx + SM_AL + oA) = lA;
        *(uint32_t*)(smx + SM_AL + oB) = lB;
    }
    #pragma unroll
    for (int nt = 0; nt < 8; nt++)
        #pragma unroll
        for (int c = 0; c < 4; c++) acc[nt][c] = 0.f;
    __syncthreads();

    // ---- GEMM 2 ----
    #pragma unroll
    for (int kt = 0; kt < 8; kt++) {
        const uint32_t aoff = kt * QKT + tg * 8;
        uint2 qah = *(const uint2*)(smx + SM_AH + aoff + rA * 32);
        uint2 qbh = *(const uint2*)(smx + SM_AH + aoff + (rA + 8) * 32);
        uint2 qal = *(const uint2*)(smx + SM_AL + aoff + rA * 32);
        uint2 qbl = *(const uint2*)(smx + SM_AL + aoff + (rA + 8) * 32);
        uint32_t ah[4] = { qah.x, qbh.x, qah.y, qbh.y };
        uint32_t al[4] = { qal.x, qbl.x, qal.y, qbl.y };
        #pragma unroll
        for (int nt = 0; nt < 8; nt++) {
            const int n = (nts + nt) * 8 + g;
            const uint32_t boff = kt * QKT + n * 32 + tg * 8;
            uint2 wh = *(const uint2*)(smx + SM_W3H + boff);
            uint2 wl = *(const uint2*)(smx + SM_W3L + boff);
            mma16816(acc[nt], ah, wh.x, wh.y);
            mma16816(acc[nt], ah, wl.x, wl.y);
            mma16816(acc[nt], al, wh.x, wh.y);
        }
    }

    // epilogue 2: bias3, partial LN sums over this half's 64 cols
    float sA = 0.f, s2A = 0.f, sB = 0.f, s2B = 0.f;
    #pragma unroll
    for (int nt = 0; nt < 8; nt++) {
        const int c0 = (nts + nt) * 8 + 2 * tg;
        float b0f = eb3s[c0], b1f = eb3s[c0 + 1];
        acc[nt][0] += b0f; acc[nt][1] += b1f;
        acc[nt][2] += b0f; acc[nt][3] += b1f;
        sA += acc[nt][0] + acc[nt][1]; s2A += acc[nt][0]*acc[nt][0] + acc[nt][1]*acc[nt][1];
        sB += acc[nt][2] + acc[nt][3]; s2B += acc[nt][2]*acc[nt][2] + acc[nt][3]*acc[nt][3];
    }
    #pragma unroll
    for (int o = 1; o <= 2; o <<= 1) {
        sA  += __shfl_xor_sync(0xffffffffu, sA,  o);
        s2A += __shfl_xor_sync(0xffffffffu, s2A, o);
        sB  += __shfl_xor_sync(0xffffffffu, sB,  o);
        s2B += __shfl_xor_sync(0xffffffffu, s2B, o);
    }
    if (tg == 0) {
        part[half * 128 + rA]     = make_float2(sA, s2A);
        part[half * 128 + rA + 8] = make_float2(sB, s2B);
    }
    __syncthreads();

    {
        float2 pa0 = part[rA], pa1 = part[128 + rA];
        float2 pb0 = part[rA + 8], pb1 = part[128 + rA + 8];
        float SA = pa0.x + pa1.x, S2Aall = pa0.y + pa1.y;
        float SB = pb0.x + pb1.x, S2Ball = pb0.y + pb1.y;
        float muA = SA * (1.0f/128.0f), vA = S2Aall * (1.0f/128.0f) - muA*muA;
        float muB = SB * (1.0f/128.0f), vB = S2Ball * (1.0f/128.0f) - muB*muB;
        float rsA = rsqrtf(vA + 1e-5f), rsB = rsqrtf(vB + 1e-5f);

        float* opA = outE + (((size_t)(b * NRES + i)) * NRES + j0 + rA) * CZ;
        float* opB = opA + 8 * CZ;
        #pragma unroll
        for (int nt = 0; nt < 8; nt++) {
            const int col = (nts + nt) * 8 + 2 * tg;
            float2 gg = *(const float2*)&egs[col];
            float2 bb = *(const float2*)&ebts[col];
            float2 o0, o1;
            o0.x = (acc[nt][0] - muA) * rsA * gg.x + bb.x;
            o0.y = (acc[nt][1] - muA) * rsA * gg.y + bb.y;
            o1.x = (acc[nt][2] - muB) * rsB * gg.x + bb.x;
            o1.y = (acc[nt][3] - muB) * rsB * gg.y + bb.y;
            *(float2*)(opA + col) = o0;
            *(float2*)(opB + col) = o1;
        }
    }
}

// ---------------- launch ----------------
extern "C" void kernel_launch(void* const* d_in, const int* in_sizes, int n_in,
                              void* d_out, int out_size)
{
    const float* atom10     = (const float*)d_in[0];
    const int*   seq_idx    = (const int*)  d_in[1];
    const float* t          = (const float*)d_in[2];
    const float* fixed_mask = (const float*)d_in[3];
    /* d_in[4] node_mask unused */
    const float* sc_trans   = (const float*)d_in[5];
    const float* sc_rots    = (const float*)d_in[6];
    const float* sc_atom14  = (const float*)d_in[7];
    const float* nw1 = (const float*)d_in[8];
    const float* nb1 = (const float*)d_in[9];
    const float* nw2 = (const float*)d_in[10];
    const float* nb2 = (const float*)d_in[11];
    const float* nw3 = (const float*)d_in[12];
    const float* nb3 = (const float*)d_in[13];
    const float* ng  = (const float*)d_in[14];
    const float* nbt = (const float*)d_in[15];
    const float* ew1 = (const float*)d_in[16];
    const float* eb1 = (const float*)d_in[17];
    const float* ew2 = (const float*)d_in[18];
    const float* eb2 = (const float*)d_in[19];
    const float* ew3 = (const float*)d_in[20];
    const float* eb3 = (const float*)d_in[21];
    const float* eg  = (const float*)d_in[22];
    const float* ebt = (const float*)d_in[23];

    float* outN = (float*)d_out;
    float* outE = outN + (size_t)BB * NRES * CS;

    cudaFuncSetAttribute(edge_kernel_mma, cudaFuncAttributeMaxDynamicSharedMemorySize,
                         SMEM_TOTAL);

    prep_w_kernel<<<2, 256>>>(ew2, ew3);
    prep_node_kernel<<<BB * NRES, 128>>>(atom10, seq_idx, t, fixed_mask,
                                         sc_trans, sc_rots, sc_atom14, ew1);
    prep_rel_kernel<<<767, 128>>>(ew1);
    node_mlp_kernel<<<BB * NRES / NROWS, 256>>>(nw1, nb1, nw2, nb2, nw3, nb3, ng, nbt, outN);
    edge_kernel_mma<<<dim3(NRES / 128, NRES, BB), 512, SMEM_TOTAL>>>(
        seq_idx, sc_trans, ew1, eb1, eb2, eb3, eg, ebt, outE);
}

// round 14
// speedup vs baseline: 1.9979x; 1.2131x over previous
#include <cuda_runtime.h>
#include <cuda_bf16.h>
#include <math.h>
#include <stdint.h>

#define BB 2
#define NRES 384
#define CS 256
#define CZ 128
#define NODE_IN 145
#define NROWS 4
#define PI_F 3.14159265358979323846f

// quad layout: quad(kt, idx, tg) holds bf16 elems k = kt*16+2tg, +1, +8, +9 for row idx
// byte addr = base + kt*QKT + idx*32 + tg*8   (QKT=4128 keeps kt blocks bank-staggered)
#define QKT 4128
#define WTILE 33024               // 8 * QKT

// smem byte offsets (edge kernel)
#define SM_W2H 0
#define SM_W2L 33024
#define SM_W3H 66048
#define SM_W3L 99072
#define SM_AH  132096
#define SM_AL  165120
#define SM_AUX 198144
#define SMEM_TOTAL (SM_AUX + 5632)

#define NTILES (BB * NRES * 3)
#define EDGE_CTAS 148

// ---------------- scratch (no allocation allowed) ----------------
__device__ float g_NIN[BB * NRES * NODE_IN];
__device__ float g_NA [BB * NRES * CZ];
__device__ float g_NB [BB * NRES * CZ];
__device__ float g_REL[767 * CZ];
__device__ __align__(16) unsigned char g_WT[4 * WTILE];   // W2h | W2l | W3h | W3l in quad layout

// ---------------- helpers ----------------
__device__ __forceinline__ uint32_t packbf(float lo, float hi) {
    uint32_t r;
    asm("cvt.rn.bf16x2.f32 %0, %1, %2;" : "=r"(r) : "f"(hi), "f"(lo));
    return r;
}
__device__ __forceinline__ void mma16816(float* c, const uint32_t* a, uint32_t b0, uint32_t b1) {
    asm volatile("mma.sync.aligned.m16n8k16.row.col.f32.bf16.bf16.f32 "
        "{%0,%1,%2,%3}, {%4,%5,%6,%7}, {%8,%9}, {%0,%1,%2,%3};"
        : "+f"(c[0]), "+f"(c[1]), "+f"(c[2]), "+f"(c[3])
        : "r"(a[0]), "r"(a[1]), "r"(a[2]), "r"(a[3]), "r"(b0), "r"(b1));
}
__device__ __forceinline__ void split2(float2 v, uint32_t& hi, uint32_t& lo) {
    hi = packbf(v.x, v.y);
    float hx = __uint_as_float(hi << 16);
    float hy = __uint_as_float(hi & 0xFFFF0000u);
    lo = packbf(v.x - hx, v.y - hy);
}

// ---------------- kernel 0: W2/W3 -> quad-layout bf16 hi/lo blob ----------------
__global__ __launch_bounds__(256) void prep_w_kernel(const float* __restrict__ ew2,
                                                     const float* __restrict__ ew3)
{
    const float* W = blockIdx.x ? ew3 : ew2;
    unsigned char* dh = g_WT + (size_t)blockIdx.x * 2 * WTILE;
    unsigned char* dl = dh + WTILE;
    for (int q = threadIdx.x; q < 8 * 128 * 4; q += 256) {
        int kt = q >> 9, rem = q & 511, n = rem >> 2, tg = rem & 3;
        int k0 = kt * 16 + 2 * tg;
        float2 va = make_float2(W[k0 * 128 + n], W[(k0 + 1) * 128 + n]);
        float2 vb = make_float2(W[(k0 + 8) * 128 + n], W[(k0 + 9) * 128 + n]);
        uint32_t ha, la, hb, lb;
        split2(va, ha, la);
        split2(vb, hb, lb);
        uint32_t off = kt * QKT + n * 32 + tg * 8;
        *(uint2*)(dh + off) = make_uint2(ha, hb);
        *(uint2*)(dl + off) = make_uint2(la, lb);
    }
}

// ---------------- kernel 1: per-node features + A/B projections ----------------
__global__ __launch_bounds__(128) void prep_node_kernel(
    const float* __restrict__ atom10, const int* __restrict__ seq_idx,
    const float* __restrict__ t, const float* __restrict__ fixed_mask,
    const float* __restrict__ sc_trans, const float* __restrict__ sc_rots,
    const float* __restrict__ sc_atom14, const float* __restrict__ ew1)
{
    __shared__ float pt[73];
    __shared__ float nin[NODE_IN];
    const int row = blockIdx.x;
    const int b = row / NRES;
    const int tid = threadIdx.x;

    if (tid < 16) {
        float fr = expf((float)tid * (-logf(10000.0f) / 15.0f));
        float ang = t[b] * 10000.0f * fr;
        pt[tid]      = sinf(ang);
        pt[16 + tid] = cosf(ang);
        float den = powf(2056.0f, (float)tid / 16.0f);
        float ang2 = (float)seq_idx[row] * PI_F / den;
        nin[73 + tid]      = sinf(ang2);
        nin[73 + 16 + tid] = cosf(ang2);
    }
    if (tid == 0) pt[32] = fixed_mask[row];
    if (tid < 30) pt[33 + tid] = atom10[row * 30 + tid];
    if (tid < 10) {
        const float* ap = atom10 + row * 30 + tid * 3;
        float x = ap[0], y = ap[1], z = ap[2];
        float d = sqrtf(x * x + y * y + z * z);
        pt[63 + tid] = 1.0f / (1.0f + d * d);
        const float* tr = sc_trans + row * 3;
        const float* R  = sc_rots  + row * 9;
        const float* at = sc_atom14 + row * 42 + (4 + tid) * 3;
        float d0 = at[0] - tr[0], d1 = at[1] - tr[1], d2 = at[2] - tr[2];
        float l0 = d0 * R[0] + d1 * R[3] + d2 * R[6];
        float l1 = d0 * R[1] + d1 * R[4] + d2 * R[7];
        float l2 = d0 * R[2] + d1 * R[5] + d2 * R[8];
        nin[105 + tid * 3 + 0] = l0;
        nin[105 + tid * 3 + 1] = l1;
        nin[105 + tid * 3 + 2] = l2;
        float ld = sqrtf(l0 * l0 + l1 * l1 + l2 * l2);
        nin[135 + tid] = 1.0f / (1.0f + ld);
    }
    __syncthreads();
    if (tid < 73) nin[tid] = pt[tid];
    __syncthreads();

    for (int x = tid; x < NODE_IN; x += 128)
        g_NIN[row * NODE_IN + x] = nin[x];

    if (tid < CZ) {
        float accA = 0.f, accB = 0.f;
        #pragma unroll 4
        for (int f = 0; f < 73; f++) {
            float p = pt[f];
            accA = fmaf(p, ew1[f * CZ + tid], accA);
            accB = fmaf(p, ew1[(73 + f) * CZ + tid], accB);
        }
        g_NA[row * CZ + tid] = accA;
        g_NB[row * CZ + tid] = accB;
    }
}

// ---------------- kernel 2: relative-position table ----------------
__global__ __launch_bounds__(128) void prep_rel_kernel(const float* __restrict__ ew1)
{
    __shared__ float emb[32];
    const int r = blockIdx.x;
    const int tid = threadIdx.x;
    if (tid < 16) {
        float v = (float)(r - 383);
        float den = powf(2056.0f, (float)tid / 16.0f);
        float ang = v * PI_F / den;
        emb[tid]      = sinf(ang);
        emb[16 + tid] = cosf(ang);
    }
    __syncthreads();
    float acc = 0.f;
    #pragma unroll
    for (int k = 0; k < 32; k++)
        acc = fmaf(emb[k], ew1[(146 + k) * CZ + tid], acc);
    g_REL[r * CZ + tid] = acc;
}

// ---------------- kernel 3: node MLP + LN (4 rows/CTA -> 192 CTAs) ----------------
__global__ __launch_bounds__(256) void node_mlp_kernel(
    const float* __restrict__ nw1, const float* __restrict__ nb1,
    const float* __restrict__ nw2, const float* __restrict__ nb2,
    const float* __restrict__ nw3, const float* __restrict__ nb3,
    const float* __restrict__ ng,  const float* __restrict__ nbt,
    float* __restrict__ outN)
{
    __shared__ float nin[NROWS][NODE_IN];
    __shared__ float h[NROWS][CS];
    __shared__ float sred[NROWS][8], s2red[NROWS][8];
    const int r0 = blockIdx.x * NROWS;
    const int tid = threadIdx.x;

    for (int x = tid; x < NROWS * NODE_IN; x += 256)
        nin[x / NODE_IN][x % NODE_IN] = g_NIN[r0 * NODE_IN + x];
    __syncthreads();

    float a[NROWS];
    #pragma unroll
    for (int r = 0; r < NROWS; r++) a[r] = nb1[tid];
    #pragma unroll 8
    for (int k = 0; k < NODE_IN; k++) {
        float w = nw1[k * CS + tid];
        #pragma unroll
        for (int r = 0; r < NROWS; r++) a[r] = fmaf(nin[r][k], w, a[r]);
    }
    #pragma unroll
    for (int r = 0; r < NROWS; r++) h[r][tid] = fmaxf(a[r], 0.f);
    __syncthreads();

    #pragma unroll
    for (int r = 0; r < NROWS; r++) a[r] = nb2[tid];
    #pragma unroll 8
    for (int k = 0; k < CS; k++) {
        float w = nw2[k * CS + tid];
        #pragma unroll
        for (int r = 0; r < NROWS; r++) a[r] = fmaf(h[r][k], w, a[r]);
    }
    __syncthreads();
    #pragma unroll
    for (int r = 0; r < NROWS; r++) h[r][tid] = fmaxf(a[r], 0.f);
    __syncthreads();

    #pragma unroll
    for (int r = 0; r < NROWS; r++) a[r] = nb3[tid];
    #pragma unroll 8
    for (int k = 0; k < CS; k++) {
        float w = nw3[k * CS + tid];
        #pragma unroll
        for (int r = 0; r < NROWS; r++) a[r] = fmaf(h[r][k], w, a[r]);
    }

    #pragma unroll
    for (int r = 0; r < NROWS; r++) {
        float s = a[r], s2 = a[r] * a[r];
        #pragma unroll
        for (int o = 16; o > 0; o >>= 1) {
            s  += __shfl_xor_sync(0xffffffffu, s,  o);
            s2 += __shfl_xor_sync(0xffffffffu, s2, o);
        }
        if ((tid & 31) == 0) { sred[r][tid >> 5] = s; s2red[r][tid >> 5] = s2; }
    }
    __syncthreads();
    float gv = ng[tid], bv = nbt[tid];
    #pragma unroll
    for (int r = 0; r < NROWS; r++) {
        float S = 0.f, S2 = 0.f;
        #pragma unroll
        for (int w = 0; w < 8; w++) { S += sred[r][w]; S2 += s2red[r][w]; }
        float mu = S * (1.0f / CS);
        float var = S2 * (1.0f / CS) - mu * mu;
        float rs = rsqrtf(var + 1e-5f);
        outN[(r0 + r) * CS + tid] = (a[r] - mu) * rs * gv + bv;
    }
}

// ---------------- kernel 4: persistent edge MLP, 16 warps, quad-layout mma.sync ----------------
__global__ __launch_bounds__(512) void edge_kernel_mma(
    const int* __restrict__ seq_idx, const float* __restrict__ sc_trans,
    const float* __restrict__ ew1, const float* __restrict__ eb1,
    const float* __restrict__ eb2, const float* __restrict__ eb3,
    const float* __restrict__ eg,  const float* __restrict__ ebt,
    float* __restrict__ outE)
{
    extern __shared__ char smx[];
    float* baseS = (float*)(smx + SM_AUX);
    float* eb2s  = baseS + 128;
    float* eb3s  = eb2s + 128;
    float* egs   = eb3s + 128;
    float* ebts  = egs  + 128;
    int*   relS  = (int*)(ebts + 128);
    int*   binS  = relS + 128;
    float2* part = (float2*)(binS + 128);   // [half][row] partial (sum, sum2), 2*128

    const int tid = threadIdx.x;
    const int w = tid >> 5, lane = tid & 31, g = lane >> 2, tg = lane & 3;
    const int mt = w & 7, half = w >> 3, nts = half * 8;
    const int rA = mt * 16 + g;

    // one-time: weights + constant vectors -> smem
    {
        const uint4* src = (const uint4*)g_WT;
        uint4* dst = (uint4*)smx;
        for (int x = tid; x < (4 * WTILE) / 16; x += 512) dst[x] = src[x];
    }
    if (tid < 128) {
        eb2s[tid] = eb2[tid]; eb3s[tid] = eb3[tid];
        egs[tid]  = eg[tid];  ebts[tid] = ebt[tid];
    }

    for (int tix = blockIdx.x; tix < NTILES; tix += gridDim.x) {
        const int b = tix / (NRES * 3);
        const int rem = tix % (NRES * 3);
        const int i = rem / 3;
        const int jt = rem % 3;
        const int j0 = jt * 128;
        const int row_i = b * NRES + i;

        // per-tile aux
        if (tid < 128) {
            baseS[tid] = g_NA[row_i * CZ + tid] + eb1[tid];
        } else if (tid < 256) {
            const int m = tid - 128;
            const int row_j = b * NRES + j0 + m;
            int r = seq_idx[row_i] - seq_idx[row_j] + 383;
            relS[m] = min(max(r, 0), 766);
            float dx = sc_trans[row_i * 3 + 0] - sc_trans[row_j * 3 + 0];
            float dy = sc_trans[row_i * 3 + 1] - sc_trans[row_j * 3 + 1];
            float dz = sc_trans[row_i * 3 + 2] - sc_trans[row_j * 3 + 2];
            float d = sqrtf(dx * dx + dy * dy + dz * dz);
            int bin = -1;
            const double step = (20.0 - 1e-05) / 21.0;
            #pragma unroll
            for (int k = 0; k < 22; k++) {
                float lo = (float)(1e-05 + k * step);
                float hi = (k < 21) ? (float)(1e-05 + (k + 1) * step) : 1e8f;
                if (d > lo && d < hi) bin = k;
            }
            binS[m] = bin;
        }
        __syncthreads();

        // build A1 quads: h1[m][k] = relu(base + NB + REL + dgram), split hi/lo
        {
            const int kt = lane >> 2;
            const int k0 = kt * 16 + 2 * tg;
            #pragma unroll
            for (int p = 0; p < 8; p++) {
                const int m = w * 8 + p;
                const int rel = relS[m], bin = binS[m];
                const float* nb = g_NB + ((size_t)(b * NRES + j0 + m)) * CZ;
                const float* rl = g_REL + (size_t)rel * CZ;
                float2 va = make_float2(baseS[k0] + nb[k0] + rl[k0],
                                        baseS[k0 + 1] + nb[k0 + 1] + rl[k0 + 1]);
                float2 vb = make_float2(baseS[k0 + 8] + nb[k0 + 8] + rl[k0 + 8],
                                        baseS[k0 + 9] + nb[k0 + 9] + rl[k0 + 9]);
                if (bin >= 0) {
                    const float* dg = ew1 + (178 + bin) * CZ;
                    va.x += dg[k0];     va.y += dg[k0 + 1];
                    vb.x += dg[k0 + 8]; vb.y += dg[k0 + 9];
                }
                va.x = fmaxf(va.x, 0.f); va.y = fmaxf(va.y, 0.f);
                vb.x = fmaxf(vb.x, 0.f); vb.y = fmaxf(vb.y, 0.f);
                uint32_t ha, la, hb, lb;
                split2(va, ha, la);
                split2(vb, hb, lb);
                const uint32_t off = kt * QKT + m * 32 + tg * 8;
                *(uint2*)(smx + SM_AH + off) = make_uint2(ha, hb);
                *(uint2*)(smx + SM_AL + off) = make_uint2(la, lb);
            }
        }
        __syncthreads();

        float acc[8][4];
        #pragma unroll
        for (int nt = 0; nt < 8; nt++)
            #pragma unroll
            for (int c = 0; c < 4; c++) acc[nt][c] = 0.f;

        // ---- GEMM 1 ----
        #pragma unroll
        for (int kt = 0; kt < 8; kt++) {
            const uint32_t aoff = kt * QKT + tg * 8;
            uint2 qah = *(const uint2*)(smx + SM_AH + aoff + rA * 32);
            uint2 qbh = *(const uint2*)(smx + SM_AH + aoff + (rA + 8) * 32);
            uint2 qal = *(const uint2*)(smx + SM_AL + aoff + rA * 32);
            uint2 qbl = *(const uint2*)(smx + SM_AL + aoff + (rA + 8) * 32);
            uint32_t ah[4] = { qah.x, qbh.x, qah.y, qbh.y };
            uint32_t al[4] = { qal.x, qbl.x, qal.y, qbl.y };
            #pragma unroll
            for (int nt = 0; nt < 8; nt++) {
                const int n = (nts + nt) * 8 + g;
                const uint32_t boff = kt * QKT + n * 32 + tg * 8;
                uint2 wh = *(const uint2*)(smx + SM_W2H + boff);
                uint2 wl = *(const uint2*)(smx + SM_W2L + boff);
                mma16816(acc[nt], ah, wh.x, wh.y);
                mma16816(acc[nt], ah, wl.x, wl.y);
                mma16816(acc[nt], al, wh.x, wh.y);
            }
        }
        __syncthreads();   // all warps done reading A1 before A2 overwrites

        // epilogue 1: bias + relu -> A2 quads (hi/lo)
        #pragma unroll
        for (int nt = 0; nt < 8; nt++) {
            const int cg = nts + nt;
            const int c0 = cg * 8 + 2 * tg;
            float b0f = eb2s[c0], b1f = eb2s[c0 + 1];
            float2 vA = make_float2(fmaxf(acc[nt][0] + b0f, 0.f), fmaxf(acc[nt][1] + b1f, 0.f));
            float2 vB = make_float2(fmaxf(acc[nt][2] + b0f, 0.f), fmaxf(acc[nt][3] + b1f, 0.f));
            uint32_t hA, lA, hB, lB;
            split2(vA, hA, lA);
            split2(vB, hB, lB);
            const int kt2 = cg >> 1;
            const int off4 = (cg & 1) * 4;
            const uint32_t oA = kt2 * QKT + rA * 32 + tg * 8 + off4;
            const uint32_t oB = kt2 * QKT + (rA + 8) * 32 + tg * 8 + off4;
            *(uint32_t*)(smx + SM_AH + oA) = hA;
            *(uint32_t*)(smx + SM_AH + oB) = hB;
            *(uint32_t*)(smx + SM_AL + oA) = lA;
            *(uint32_t*)(smx + SM_AL + oB) = lB;
        }
        #pragma unroll
        for (int nt = 0; nt < 8; nt++)
            #pragma unroll
            for (int c = 0; c < 4; c++) acc[nt][c] = 0.f;
        __syncthreads();

        // ---- GEMM 2 ----
        #pragma unroll
        for (int kt = 0; kt < 8; kt++) {
            const uint32_t aoff = kt * QKT + tg * 8;
            uint2 qah = *(const uint2*)(smx + SM_AH + aoff + rA * 32);
            uint2 qbh = *(const uint2*)(smx + SM_AH + aoff + (rA + 8) * 32);
            uint2 qal = *(const uint2*)(smx + SM_AL + aoff + rA * 32);
            uint2 qbl = *(const uint2*)(smx + SM_AL + aoff + (rA + 8) * 32);
            uint32_t ah[4] = { qah.x, qbh.x, qah.y, qbh.y };
            uint32_t al[4] = { qal.x, qbl.x, qal.y, qbl.y };
            #pragma unroll
            for (int nt = 0; nt < 8; nt++) {
                const int n = (nts + nt) * 8 + g;
                const uint32_t boff = kt * QKT + n * 32 + tg * 8;
                uint2 wh = *(const uint2*)(smx + SM_W3H + boff);
                uint2 wl = *(const uint2*)(smx + SM_W3L + boff);
                mma16816(acc[nt], ah, wh.x, wh.y);
                mma16816(acc[nt], ah, wl.x, wl.y);
                mma16816(acc[nt], al, wh.x, wh.y);
            }
        }

        // epilogue 2: bias3 + partial LN sums over this half's 64 cols
        float sA = 0.f, s2A = 0.f, sB = 0.f, s2B = 0.f;
        #pragma unroll
        for (int nt = 0; nt < 8; nt++) {
            const int c0 = (nts + nt) * 8 + 2 * tg;
            float b0f = eb3s[c0], b1f = eb3s[c0 + 1];
            acc[nt][0] += b0f; acc[nt][1] += b1f;
            acc[nt][2] += b0f; acc[nt][3] += b1f;
            sA += acc[nt][0] + acc[nt][1]; s2A += acc[nt][0]*acc[nt][0] + acc[nt][1]*acc[nt][1];
            sB += acc[nt][2] + acc[nt][3]; s2B += acc[nt][2]*acc[nt][2] + acc[nt][3]*acc[nt][3];
        }
        #pragma unroll
        for (int o = 1; o <= 2; o <<= 1) {
            sA  += __shfl_xor_sync(0xffffffffu, sA,  o);
            s2A += __shfl_xor_sync(0xffffffffu, s2A, o);
            sB  += __shfl_xor_sync(0xffffffffu, sB,  o);
            s2B += __shfl_xor_sync(0xffffffffu, s2B, o);
        }
        if (tg == 0) {
            part[half * 128 + rA]     = make_float2(sA, s2A);
            part[half * 128 + rA + 8] = make_float2(sB, s2B);
        }
        __syncthreads();

        {
            float2 pa0 = part[rA], pa1 = part[128 + rA];
            float2 pb0 = part[rA + 8], pb1 = part[128 + rA + 8];
            float SA = pa0.x + pa1.x, S2Aall = pa0.y + pa1.y;
            float SB = pb0.x + pb1.x, S2Ball = pb0.y + pb1.y;
            float muA = SA * (1.0f/128.0f), vA = S2Aall * (1.0f/128.0f) - muA*muA;
            float muB = SB * (1.0f/128.0f), vB = S2Ball * (1.0f/128.0f) - muB*muB;
            float rsA = rsqrtf(vA + 1e-5f), rsB = rsqrtf(vB + 1e-5f);

            float* opA = outE + (((size_t)(b * NRES + i)) * NRES + j0 + rA) * CZ;
            float* opB = opA + 8 * CZ;
            #pragma unroll
            for (int nt = 0; nt < 8; nt++) {
                const int col = (nts + nt) * 8 + 2 * tg;
                float2 gg = *(const float2*)&egs[col];
                float2 bb = *(const float2*)&ebts[col];
                float2 o0, o1;
                o0.x = (acc[nt][0] - muA) * rsA * gg.x + bb.x;
                o0.y = (acc[nt][1] - muA) * rsA * gg.y + bb.y;
                o1.x = (acc[nt][2] - muB) * rsB * gg.x + bb.x;
                o1.y = (acc[nt][3] - muB) * rsB * gg.y + bb.y;
                *(float2*)(opA + col) = o0;
                *(float2*)(opB + col) = o1;
            }
        }
    }
}

// ---------------- launch ----------------
extern "C" void kernel_launch(void* const* d_in, const int* in_sizes, int n_in,
                              void* d_out, int out_size)
{
    const float* atom10     = (const float*)d_in[0];
    const int*   seq_idx    = (const int*)  d_in[1];
    const float* t          = (const float*)d_in[2];
    const float* fixed_mask = (const float*)d_in[3];
    /* d_in[4] node_mask unused */
    const float* sc_trans   = (const float*)d_in[5];
    const float* sc_rots    = (const float*)d_in[6];
    const float* sc_atom14  = (const float*)d_in[7];
    const float* nw1 = (const float*)d_in[8];
    const float* nb1 = (const float*)d_in[9];
    const float* nw2 = (const float*)d_in[10];
    const float* nb2 = (const float*)d_in[11];
    const float* nw3 = (const float*)d_in[12];
    const float* nb3 = (const float*)d_in[13];
    const float* ng  = (const float*)d_in[14];
    const float* nbt = (const float*)d_in[15];
    const float* ew1 = (const float*)d_in[16];
    const float* eb1 = (const float*)d_in[17];
    const float* ew2 = (const float*)d_in[18];
    const float* eb2 = (const float*)d_in[19];
    const float* ew3 = (const float*)d_in[20];
    const float* eb3 = (const float*)d_in[21];
    const float* eg  = (const float*)d_in[22];
    const float* ebt = (const float*)d_in[23];

    float* outN = (float*)d_out;
    float* outE = outN + (size_t)BB * NRES * CS;

    cudaFuncSetAttribute(edge_kernel_mma, cudaFuncAttributeMaxDynamicSharedMemorySize,
                         SMEM_TOTAL);

    prep_w_kernel<<<2, 256>>>(ew2, ew3);
    prep_node_kernel<<<BB * NRES, 128>>>(atom10, seq_idx, t, fixed_mask,
                                         sc_trans, sc_rots, sc_atom14, ew1);
    prep_rel_kernel<<<767, 128>>>(ew1);
    node_mlp_kernel<<<BB * NRES / NROWS, 256>>>(nw1, nb1, nw2, nb2, nw3, nb3, ng, nbt, outN);
    edge_kernel_mma<<<EDGE_CTAS, 512, SMEM_TOTAL>>>(
        seq_idx, sc_trans, ew1, eb1, eb2, eb3, eg, ebt, outE);
}

// round 17
// speedup vs baseline: 2.1835x; 1.0929x over previous
#include <cuda_runtime.h>
#include <cuda_bf16.h>
#include <math.h>
#include <stdint.h>

#define BB 2
#define NRES 384
#define CS 256
#define CZ 128
#define NODE_IN 145
#define NROWS 4
#define PI_F 3.14159265358979323846f

// quad layout: quad(kt, idx, tg) holds bf16 elems k = kt*16+2tg, +1, +8, +9 for row idx
// byte addr = base + kt*QKT + idx*32 + tg*8   (QKT=4128 keeps kt blocks bank-staggered)
#define QKT 4128
#define WTILE 33024               // 8 * QKT

// smem byte offsets (edge kernel)
#define SM_W2H 0
#define SM_W2L 33024
#define SM_W3H 66048
#define SM_W3L 99072
#define SM_AH  132096
#define SM_AL  165120
#define SM_AUX 198144
#define SMEM_TOTAL (SM_AUX + 5632)

#define NTILES (BB * NRES * 3)
#define EDGE_CTAS 148

// ---------------- scratch (no allocation allowed) ----------------
__device__ float g_NIN[BB * NRES * NODE_IN];
__device__ float g_NA [BB * NRES * CZ];
__device__ float g_NB [BB * NRES * CZ];
__device__ float g_REL[767 * CZ];
__device__ __align__(16) unsigned char g_WT[4 * WTILE];   // W2h | W2l | W3h | W3l in quad layout

// ---------------- helpers ----------------
__device__ __forceinline__ uint32_t packbf(float lo, float hi) {
    uint32_t r;
    asm("cvt.rn.bf16x2.f32 %0, %1, %2;" : "=r"(r) : "f"(hi), "f"(lo));
    return r;
}
__device__ __forceinline__ void mma16816(float* c, const uint32_t* a, uint32_t b0, uint32_t b1) {
    asm volatile("mma.sync.aligned.m16n8k16.row.col.f32.bf16.bf16.f32 "
        "{%0,%1,%2,%3}, {%4,%5,%6,%7}, {%8,%9}, {%0,%1,%2,%3};"
        : "+f"(c[0]), "+f"(c[1]), "+f"(c[2]), "+f"(c[3])
        : "r"(a[0]), "r"(a[1]), "r"(a[2]), "r"(a[3]), "r"(b0), "r"(b1));
}
__device__ __forceinline__ void split2(float2 v, uint32_t& hi, uint32_t& lo) {
    hi = packbf(v.x, v.y);
    float hx = __uint_as_float(hi << 16);
    float hy = __uint_as_float(hi & 0xFFFF0000u);
    lo = packbf(v.x - hx, v.y - hy);
}

// ---------------- kernel 0: W2/W3 -> quad-layout bf16 hi/lo blob ----------------
__global__ __launch_bounds__(256) void prep_w_kernel(const float* __restrict__ ew2,
                                                     const float* __restrict__ ew3)
{
    const float* W = blockIdx.x ? ew3 : ew2;
    unsigned char* dh = g_WT + (size_t)blockIdx.x * 2 * WTILE;
    unsigned char* dl = dh + WTILE;
    for (int q = threadIdx.x; q < 8 * 128 * 4; q += 256) {
        int kt = q >> 9, rem = q & 511, n = rem >> 2, tg = rem & 3;
        int k0 = kt * 16 + 2 * tg;
        float2 va = make_float2(W[k0 * 128 + n], W[(k0 + 1) * 128 + n]);
        float2 vb = make_float2(W[(k0 + 8) * 128 + n], W[(k0 + 9) * 128 + n]);
        uint32_t ha, la, hb, lb;
        split2(va, ha, la);
        split2(vb, hb, lb);
        uint32_t off = kt * QKT + n * 32 + tg * 8;
        *(uint2*)(dh + off) = make_uint2(ha, hb);
        *(uint2*)(dl + off) = make_uint2(la, lb);
    }
}

// ---------------- kernel 1: per-node features + A/B projections ----------------
__global__ __launch_bounds__(128) void prep_node_kernel(
    const float* __restrict__ atom10, const int* __restrict__ seq_idx,
    const float* __restrict__ t, const float* __restrict__ fixed_mask,
    const float* __restrict__ sc_trans, const float* __restrict__ sc_rots,
    const float* __restrict__ sc_atom14, const float* __restrict__ ew1)
{
    __shared__ float pt[73];
    __shared__ float nin[NODE_IN];
    const int row = blockIdx.x;
    const int b = row / NRES;
    const int tid = threadIdx.x;

    if (tid < 16) {
        float fr = expf((float)tid * (-logf(10000.0f) / 15.0f));
        float ang = t[b] * 10000.0f * fr;
        pt[tid]      = sinf(ang);
        pt[16 + tid] = cosf(ang);
        float den = powf(2056.0f, (float)tid / 16.0f);
        float ang2 = (float)seq_idx[row] * PI_F / den;
        nin[73 + tid]      = sinf(ang2);
        nin[73 + 16 + tid] = cosf(ang2);
    }
    if (tid == 0) pt[32] = fixed_mask[row];
    if (tid < 30) pt[33 + tid] = atom10[row * 30 + tid];
    if (tid < 10) {
        const float* ap = atom10 + row * 30 + tid * 3;
        float x = ap[0], y = ap[1], z = ap[2];
        float d = sqrtf(x * x + y * y + z * z);
        pt[63 + tid] = 1.0f / (1.0f + d * d);
        const float* tr = sc_trans + row * 3;
        const float* R  = sc_rots  + row * 9;
        const float* at = sc_atom14 + row * 42 + (4 + tid) * 3;
        float d0 = at[0] - tr[0], d1 = at[1] - tr[1], d2 = at[2] - tr[2];
        float l0 = d0 * R[0] + d1 * R[3] + d2 * R[6];
        float l1 = d0 * R[1] + d1 * R[4] + d2 * R[7];
        float l2 = d0 * R[2] + d1 * R[5] + d2 * R[8];
        nin[105 + tid * 3 + 0] = l0;
        nin[105 + tid * 3 + 1] = l1;
        nin[105 + tid * 3 + 2] = l2;
        float ld = sqrtf(l0 * l0 + l1 * l1 + l2 * l2);
        nin[135 + tid] = 1.0f / (1.0f + ld);
    }
    __syncthreads();
    if (tid < 73) nin[tid] = pt[tid];
    __syncthreads();

    for (int x = tid; x < NODE_IN; x += 128)
        g_NIN[row * NODE_IN + x] = nin[x];

    if (tid < CZ) {
        float accA = 0.f, accB = 0.f;
        #pragma unroll 4
        for (int f = 0; f < 73; f++) {
            float p = pt[f];
            accA = fmaf(p, ew1[f * CZ + tid], accA);
            accB = fmaf(p, ew1[(73 + f) * CZ + tid], accB);
        }
        g_NA[row * CZ + tid] = accA;
        g_NB[row * CZ + tid] = accB;
    }
}

// ---------------- kernel 2: relative-position table ----------------
__global__ __launch_bounds__(128) void prep_rel_kernel(const float* __restrict__ ew1)
{
    __shared__ float emb[32];
    const int r = blockIdx.x;
    const int tid = threadIdx.x;
    if (tid < 16) {
        float v = (float)(r - 383);
        float den = powf(2056.0f, (float)tid / 16.0f);
        float ang = v * PI_F / den;
        emb[tid]      = sinf(ang);
        emb[16 + tid] = cosf(ang);
    }
    __syncthreads();
    float acc = 0.f;
    #pragma unroll
    for (int k = 0; k < 32; k++)
        acc = fmaf(emb[k], ew1[(146 + k) * CZ + tid], acc);
    g_REL[r * CZ + tid] = acc;
}

// ---------------- kernel 3: node MLP + LN, k-split x4 with float4 weight loads ----------------
// 256 threads = 64 col-groups(4 cols) x 4 k-quarters. 4 rows/CTA -> 192 CTAs.
__global__ __launch_bounds__(256) void node_mlp_kernel(
    const float* __restrict__ nw1, const float* __restrict__ nb1,
    const float* __restrict__ nw2, const float* __restrict__ nb2,
    const float* __restrict__ nw3, const float* __restrict__ nb3,
    const float* __restrict__ ng,  const float* __restrict__ nbt,
    float* __restrict__ outN)
{
    __shared__ float nin[NROWS][NODE_IN + 3];
    __shared__ float h[NROWS][CS];
    __shared__ float part[4][NROWS][CS];
    __shared__ float sred[NROWS][8], s2red[NROWS][8];
    const int r0 = blockIdx.x * NROWS;
    const int tid = threadIdx.x;
    const int c4 = (tid & 63) * 4;   // first of 4 columns
    const int kq = tid >> 6;         // k quarter 0..3

    for (int x = tid; x < NROWS * NODE_IN; x += 256)
        nin[x / NODE_IN][x % NODE_IN] = g_NIN[r0 * NODE_IN + x];
    __syncthreads();

    float acc[NROWS][4];

    // ---- layer 1: NODE_IN -> CS ----
    {
        #pragma unroll
        for (int r = 0; r < NROWS; r++)
            #pragma unroll
            for (int c = 0; c < 4; c++) acc[r][c] = 0.f;
        const int ks = (kq * NODE_IN) >> 2, ke = ((kq + 1) * NODE_IN) >> 2;
        #pragma unroll 4
        for (int k = ks; k < ke; k++) {
            float4 w4 = *(const float4*)&nw1[k * CS + c4];
            #pragma unroll
            for (int r = 0; r < NROWS; r++) {
                float f = nin[r][k];
                acc[r][0] = fmaf(f, w4.x, acc[r][0]);
                acc[r][1] = fmaf(f, w4.y, acc[r][1]);
                acc[r][2] = fmaf(f, w4.z, acc[r][2]);
                acc[r][3] = fmaf(f, w4.w, acc[r][3]);
            }
        }
        #pragma unroll
        for (int r = 0; r < NROWS; r++)
            *(float4*)&part[kq][r][c4] = make_float4(acc[r][0], acc[r][1], acc[r][2], acc[r][3]);
        __syncthreads();
        const int col = tid;
        float bb = nb1[col];
        #pragma unroll
        for (int r = 0; r < NROWS; r++)
            h[r][col] = fmaxf(part[0][r][col] + part[1][r][col]
                            + part[2][r][col] + part[3][r][col] + bb, 0.f);
        __syncthreads();
    }

    // ---- layer 2: CS -> CS ----
    {
        #pragma unroll
        for (int r = 0; r < NROWS; r++)
            #pragma unroll
            for (int c = 0; c < 4; c++) acc[r][c] = 0.f;
        const int ks = kq * 64, ke = ks + 64;
        #pragma unroll 4
        for (int k = ks; k < ke; k++) {
            float4 w4 = *(const float4*)&nw2[k * CS + c4];
            #pragma unroll
            for (int r = 0; r < NROWS; r++) {
                float f = h[r][k];
                acc[r][0] = fmaf(f, w4.x, acc[r][0]);
                acc[r][1] = fmaf(f, w4.y, acc[r][1]);
                acc[r][2] = fmaf(f, w4.z, acc[r][2]);
                acc[r][3] = fmaf(f, w4.w, acc[r][3]);
            }
        }
        #pragma unroll
        for (int r = 0; r < NROWS; r++)
            *(float4*)&part[kq][r][c4] = make_float4(acc[r][0], acc[r][1], acc[r][2], acc[r][3]);
        __syncthreads();
        const int col = tid;
        float bb = nb2[col];
        float hv[NROWS];
        #pragma unroll
        for (int r = 0; r < NROWS; r++)
            hv[r] = fmaxf(part[0][r][col] + part[1][r][col]
                        + part[2][r][col] + part[3][r][col] + bb, 0.f);
        __syncthreads();    // all partial reads done before h overwrite
        #pragma unroll
        for (int r = 0; r < NROWS; r++) h[r][col] = hv[r];
        __syncthreads();
    }

    // ---- layer 3: CS -> CS ----
    {
        #pragma unroll
        for (int r = 0; r < NROWS; r++)
            #pragma unroll
            for (int c = 0; c < 4; c++) acc[r][c] = 0.f;
        const int ks = kq * 64, ke = ks + 64;
        #pragma unroll 4
        for (int k = ks; k < ke; k++) {
            float4 w4 = *(const float4*)&nw3[k * CS + c4];
            #pragma unroll
            for (int r = 0; r < NROWS; r++) {
                float f = h[r][k];
                acc[r][0] = fmaf(f, w4.x, acc[r][0]);
                acc[r][1] = fmaf(f, w4.y, acc[r][1]);
                acc[r][2] = fmaf(f, w4.z, acc[r][2]);
                acc[r][3] = fmaf(f, w4.w, acc[r][3]);
            }
        }
        #pragma unroll
        for (int r = 0; r < NROWS; r++)
            *(float4*)&part[kq][r][c4] = make_float4(acc[r][0], acc[r][1], acc[r][2], acc[r][3]);
        __syncthreads();
    }

    // per-col final value + LayerNorm over 256
    const int col = tid;
    float a[NROWS];
    {
        float bb = nb3[col];
        #pragma unroll
        for (int r = 0; r < NROWS; r++)
            a[r] = part[0][r][col] + part[1][r][col]
                 + part[2][r][col] + part[3][r][col] + bb;
    }
    #pragma unroll
    for (int r = 0; r < NROWS; r++) {
        float s = a[r], s2 = a[r] * a[r];
        #pragma unroll
        for (int o = 16; o > 0; o >>= 1) {
            s  += __shfl_xor_sync(0xffffffffu, s,  o);
            s2 += __shfl_xor_sync(0xffffffffu, s2, o);
        }
        if ((col & 31) == 0) { sred[r][col >> 5] = s; s2red[r][col >> 5] = s2; }
    }
    __syncthreads();
    float gv = ng[col], bv = nbt[col];
    #pragma unroll
    for (int r = 0; r < NROWS; r++) {
        float S = 0.f, S2 = 0.f;
        #pragma unroll
        for (int w = 0; w < 8; w++) { S += sred[r][w]; S2 += s2red[r][w]; }
        float mu = S * (1.0f / CS);
        float var = S2 * (1.0f / CS) - mu * mu;
        float rs = rsqrtf(var + 1e-5f);
        outN[(r0 + r) * CS + col] = (a[r] - mu) * rs * gv + bv;
    }
}

// ---------------- kernel 4: persistent edge MLP, 16 warps, quad-layout mma.sync ----------------
__global__ __launch_bounds__(512) void edge_kernel_mma(
    const int* __restrict__ seq_idx, const float* __restrict__ sc_trans,
    const float* __restrict__ ew1, const float* __restrict__ eb1,
    const float* __restrict__ eb2, const float* __restrict__ eb3,
    const float* __restrict__ eg,  const float* __restrict__ ebt,
    float* __restrict__ outE)
{
    extern __shared__ char smx[];
    float* baseS = (float*)(smx + SM_AUX);
    float* eb2s  = baseS + 128;
    float* eb3s  = eb2s + 128;
    float* egs   = eb3s + 128;
    float* ebts  = egs  + 128;
    int*   relS  = (int*)(ebts + 128);
    int*   binS  = relS + 128;
    float2* part = (float2*)(binS + 128);   // [half][row] partial (sum, sum2), 2*128

    const int tid = threadIdx.x;
    const int w = tid >> 5, lane = tid & 31, g = lane >> 2, tg = lane & 3;
    const int mt = w & 7, half = w >> 3, nts = half * 8;
    const int rA = mt * 16 + g;

    // one-time: weights + constant vectors -> smem
    {
        const uint4* src = (const uint4*)g_WT;
        uint4* dst = (uint4*)smx;
        for (int x = tid; x < (4 * WTILE) / 16; x += 512) dst[x] = src[x];
    }
    if (tid < 128) {
        eb2s[tid] = eb2[tid]; eb3s[tid] = eb3[tid];
        egs[tid]  = eg[tid];  ebts[tid] = ebt[tid];
    }

    for (int tix = blockIdx.x; tix < NTILES; tix += gridDim.x) {
        const int b = tix / (NRES * 3);
        const int rem = tix % (NRES * 3);
        const int i = rem / 3;
        const int jt = rem % 3;
        const int j0 = jt * 128;
        const int row_i = b * NRES + i;

        // per-tile aux
        if (tid < 128) {
            baseS[tid] = g_NA[row_i * CZ + tid] + eb1[tid];
        } else if (tid < 256) {
            const int m = tid - 128;
            const int row_j = b * NRES + j0 + m;
            int r = seq_idx[row_i] - seq_idx[row_j] + 383;
            relS[m] = min(max(r, 0), 766);
            float dx = sc_trans[row_i * 3 + 0] - sc_trans[row_j * 3 + 0];
            float dy = sc_trans[row_i * 3 + 1] - sc_trans[row_j * 3 + 1];
            float dz = sc_trans[row_i * 3 + 2] - sc_trans[row_j * 3 + 2];
            float d = sqrtf(dx * dx + dy * dy + dz * dz);
            int bin = -1;
            const double step = (20.0 - 1e-05) / 21.0;
            #pragma unroll
            for (int k = 0; k < 22; k++) {
                float lo = (float)(1e-05 + k * step);
                float hi = (k < 21) ? (float)(1e-05 + (k + 1) * step) : 1e8f;
                if (d > lo && d < hi) bin = k;
            }
            binS[m] = bin;
        }
        __syncthreads();

        // build A1 quads: h1[m][k] = relu(base + NB + REL + dgram), split hi/lo
        {
            const int kt = lane >> 2;
            const int k0 = kt * 16 + 2 * tg;
            #pragma unroll
            for (int p = 0; p < 8; p++) {
                const int m = w * 8 + p;
                const int rel = relS[m], bin = binS[m];
                const float* nb = g_NB + ((size_t)(b * NRES + j0 + m)) * CZ;
                const float* rl = g_REL + (size_t)rel * CZ;
                float2 va = make_float2(baseS[k0] + nb[k0] + rl[k0],
                                        baseS[k0 + 1] + nb[k0 + 1] + rl[k0 + 1]);
                float2 vb = make_float2(baseS[k0 + 8] + nb[k0 + 8] + rl[k0 + 8],
                                        baseS[k0 + 9] + nb[k0 + 9] + rl[k0 + 9]);
                if (bin >= 0) {
                    const float* dg = ew1 + (178 + bin) * CZ;
                    va.x += dg[k0];     va.y += dg[k0 + 1];
                    vb.x += dg[k0 + 8]; vb.y += dg[k0 + 9];
                }
                va.x = fmaxf(va.x, 0.f); va.y = fmaxf(va.y, 0.f);
                vb.x = fmaxf(vb.x, 0.f); vb.y = fmaxf(vb.y, 0.f);
                uint32_t ha, la, hb, lb;
                split2(va, ha, la);
                split2(vb, hb, lb);
                const uint32_t off = kt * QKT + m * 32 + tg * 8;
                *(uint2*)(smx + SM_AH + off) = make_uint2(ha, hb);
                *(uint2*)(smx + SM_AL + off) = make_uint2(la, lb);
            }
        }
        __syncthreads();

        float acc[8][4];
        #pragma unroll
        for (int nt = 0; nt < 8; nt++)
            #pragma unroll
            for (int c = 0; c < 4; c++) acc[nt][c] = 0.f;

        // ---- GEMM 1 ----
        #pragma unroll
        for (int kt = 0; kt < 8; kt++) {
            const uint32_t aoff = kt * QKT + tg * 8;
            uint2 qah = *(const uint2*)(smx + SM_AH + aoff + rA * 32);
            uint2 qbh = *(const uint2*)(smx + SM_AH + aoff + (rA + 8) * 32);
            uint2 qal = *(const uint2*)(smx + SM_AL + aoff + rA * 32);
            uint2 qbl = *(const uint2*)(smx + SM_AL + aoff + (rA + 8) * 32);
            uint32_t ah[4] = { qah.x, qbh.x, qah.y, qbh.y };
            uint32_t al[4] = { qal.x, qbl.x, qal.y, qbl.y };
            #pragma unroll
            for (int nt = 0; nt < 8; nt++) {
                const int n = (nts + nt) * 8 + g;
                const uint32_t boff = kt * QKT + n * 32 + tg * 8;
                uint2 wh = *(const uint2*)(smx + SM_W2H + boff);
                uint2 wl = *(const uint2*)(smx + SM_W2L + boff);
                mma16816(acc[nt], ah, wh.x, wh.y);
                mma16816(acc[nt], ah, wl.x, wl.y);
                mma16816(acc[nt], al, wh.x, wh.y);
            }
        }
        __syncthreads();   // all warps done reading A1 before A2 overwrites

        // epilogue 1: bias + relu -> A2 quads (hi/lo)
        #pragma unroll
        for (int nt = 0; nt < 8; nt++) {
            const int cg = nts + nt;
            const int c0 = cg * 8 + 2 * tg;
            float b0f = eb2s[c0], b1f = eb2s[c0 + 1];
            float2 vA = make_float2(fmaxf(acc[nt][0] + b0f, 0.f), fmaxf(acc[nt][1] + b1f, 0.f));
            float2 vB = make_float2(fmaxf(acc[nt][2] + b0f, 0.f), fmaxf(acc[nt][3] + b1f, 0.f));
            uint32_t hA, lA, hB, lB;
            split2(vA, hA, lA);
            split2(vB, hB, lB);
            const int kt2 = cg >> 1;
            const int off4 = (cg & 1) * 4;
            const uint32_t oA = kt2 * QKT + rA * 32 + tg * 8 + off4;
            const uint32_t oB = kt2 * QKT + (rA + 8) * 32 + tg * 8 + off4;
            *(uint32_t*)(smx + SM_AH + oA) = hA;
            *(uint32_t*)(smx + SM_AH + oB) = hB;
            *(uint32_t*)(smx + SM_AL + oA) = lA;
            *(uint32_t*)(smx + SM_AL + oB) = lB;
        }
        #pragma unroll
        for (int nt = 0; nt < 8; nt++)
            #pragma unroll
            for (int c = 0; c < 4; c++) acc[nt][c] = 0.f;
        __syncthreads();

        // ---- GEMM 2 ----
        #pragma unroll
        for (int kt = 0; kt < 8; kt++) {
            const uint32_t aoff = kt * QKT + tg * 8;
            uint2 qah = *(const uint2*)(smx + SM_AH + aoff + rA * 32);
            uint2 qbh = *(const uint2*)(smx + SM_AH + aoff + (rA + 8) * 32);
            uint2 qal = *(const uint2*)(smx + SM_AL + aoff + rA * 32);
            uint2 qbl = *(const uint2*)(smx + SM_AL + aoff + (rA + 8) * 32);
            uint32_t ah[4] = { qah.x, qbh.x, qah.y, qbh.y };
            uint32_t al[4] = { qal.x, qbl.x, qal.y, qbl.y };
            #pragma unroll
            for (int nt = 0; nt < 8; nt++) {
                const int n = (nts + nt) * 8 + g;
                const uint32_t boff = kt * QKT + n * 32 + tg * 8;
                uint2 wh = *(const uint2*)(smx + SM_W3H + boff);
                uint2 wl = *(const uint2*)(smx + SM_W3L + boff);
                mma16816(acc[nt], ah, wh.x, wh.y);
                mma16816(acc[nt], ah, wl.x, wl.y);
                mma16816(acc[nt], al, wh.x, wh.y);
            }
        }

        // epilogue 2: bias3 + partial LN sums over this half's 64 cols
        float sA = 0.f, s2A = 0.f, sB = 0.f, s2B = 0.f;
        #pragma unroll
        for (int nt = 0; nt < 8; nt++) {
            const int c0 = (nts + nt) * 8 + 2 * tg;
            float b0f = eb3s[c0], b1f = eb3s[c0 + 1];
            acc[nt][0] += b0f; acc[nt][1] += b1f;
            acc[nt][2] += b0f; acc[nt][3] += b1f;
            sA += acc[nt][0] + acc[nt][1]; s2A += acc[nt][0]*acc[nt][0] + acc[nt][1]*acc[nt][1];
            sB += acc[nt][2] + acc[nt][3]; s2B += acc[nt][2]*acc[nt][2] + acc[nt][3]*acc[nt][3];
        }
        #pragma unroll
        for (int o = 1; o <= 2; o <<= 1) {
            sA  += __shfl_xor_sync(0xffffffffu, sA,  o);
            s2A += __shfl_xor_sync(0xffffffffu, s2A, o);
            sB  += __shfl_xor_sync(0xffffffffu, sB,  o);
            s2B += __shfl_xor_sync(0xffffffffu, s2B, o);
        }
        if (tg == 0) {
            part[half * 128 + rA]     = make_float2(sA, s2A);
            part[half * 128 + rA + 8] = make_float2(sB, s2B);
        }
        __syncthreads();

        {
            float2 pa0 = part[rA], pa1 = part[128 + rA];
            float2 pb0 = part[rA + 8], pb1 = part[128 + rA + 8];
            float SA = pa0.x + pa1.x, S2Aall = pa0.y + pa1.y;
            float SB = pb0.x + pb1.x, S2Ball = pb0.y + pb1.y;
            float muA = SA * (1.0f/128.0f), vA = S2Aall * (1.0f/128.0f) - muA*muA;
            float muB = SB * (1.0f/128.0f), vB = S2Ball * (1.0f/128.0f) - muB*muB;
            float rsA = rsqrtf(vA + 1e-5f), rsB = rsqrtf(vB + 1e-5f);

            float* opA = outE + (((size_t)(b * NRES + i)) * NRES + j0 + rA) * CZ;
            float* opB = opA + 8 * CZ;
            #pragma unroll
            for (int nt = 0; nt < 8; nt++) {
                const int col = (nts + nt) * 8 + 2 * tg;
                float2 gg = *(const float2*)&egs[col];
                float2 bb = *(const float2*)&ebts[col];
                float2 o0, o1;
                o0.x = (acc[nt][0] - muA) * rsA * gg.x + bb.x;
                o0.y = (acc[nt][1] - muA) * rsA * gg.y + bb.y;
                o1.x = (acc[nt][2] - muB) * rsB * gg.x + bb.x;
                o1.y = (acc[nt][3] - muB) * rsB * gg.y + bb.y;
                *(float2*)(opA + col) = o0;
                *(float2*)(opB + col) = o1;
            }
        }
    }
}

// ---------------- launch ----------------
extern "C" void kernel_launch(void* const* d_in, const int* in_sizes, int n_in,
                              void* d_out, int out_size)
{
    const float* atom10     = (const float*)d_in[0];
    const int*   seq_idx    = (const int*)  d_in[1];
    const float* t          = (const float*)d_in[2];
    const float* fixed_mask = (const float*)d_in[3];
    /* d_in[4] node_mask unused */
    const float* sc_trans   = (const float*)d_in[5];
    const float* sc_rots    = (const float*)d_in[6];
    const float* sc_atom14  = (const float*)d_in[7];
    const float* nw1 = (const float*)d_in[8];
    const float* nb1 = (const float*)d_in[9];
    const float* nw2 = (const float*)d_in[10];
    const float* nb2 = (const float*)d_in[11];
    const float* nw3 = (const float*)d_in[12];
    const float* nb3 = (const float*)d_in[13];
    const float* ng  = (const float*)d_in[14];
    const float* nbt = (const float*)d_in[15];
    const float* ew1 = (const float*)d_in[16];
    const float* eb1 = (const float*)d_in[17];
    const float* ew2 = (const float*)d_in[18];
    const float* eb2 = (const float*)d_in[19];
    const float* ew3 = (const float*)d_in[20];
    const float* eb3 = (const float*)d_in[21];
    const float* eg  = (const float*)d_in[22];
    const float* ebt = (const float*)d_in[23];

    float* outN = (float*)d_out;
    float* outE = outN + (size_t)BB * NRES * CS;

    cudaFuncSetAttribute(edge_kernel_mma, cudaFuncAttributeMaxDynamicSharedMemorySize,
                         SMEM_TOTAL);

    prep_w_kernel<<<2, 256>>>(ew2, ew3);
    prep_node_kernel<<<BB * NRES, 128>>>(atom10, seq_idx, t, fixed_mask,
                                         sc_trans, sc_rots, sc_atom14, ew1);
    prep_rel_kernel<<<767, 128>>>(ew1);
    node_mlp_kernel<<<BB * NRES / NROWS, 256>>>(nw1, nb1, nw2, nb2, nw3, nb3, ng, nbt, outN);
    edge_kernel_mma<<<EDGE_CTAS, 512, SMEM_TOTAL>>>(
        seq_idx, sc_trans, ew1, eb1, eb2, eb3, eg, ebt, outE);
}